// round 1
// baseline (speedup 1.0000x reference)
#include <cuda_runtime.h>
#include <math.h>

// Problem dims (fixed by dataset)
#define BROWS 4096
#define HDIM  4096
#define DIN   2048
#define H1DIM 2048
#define H2DIM 1024
#define OUTD  1000
#define TEMP_INV 2.0f   // 1/TEMPERATURE

// ---------------- scratch (static device globals; no allocs allowed) --------
__device__ float g_S [(size_t)BROWS * HDIM];   // logits -> softmax (in place)
__device__ float g_h1[(size_t)BROWS * H1DIM];
__device__ float g_h2[(size_t)BROWS * H2DIM];
__device__ float g_x2[BROWS];
__device__ float g_w2[HDIM];

// ---------------- row sum-of-squares ---------------------------------------
__global__ void rowsq_kernel(const float* __restrict__ A, float* __restrict__ out, int K)
{
    int row = blockIdx.x;
    const float* p = A + (size_t)row * K;
    float s = 0.f;
    for (int i = threadIdx.x; i < K; i += 256) {
        float v = p[i];
        s = fmaf(v, v, s);
    }
    __shared__ float red[256];
    red[threadIdx.x] = s;
    __syncthreads();
    for (int st = 128; st > 0; st >>= 1) {
        if (threadIdx.x < st) red[threadIdx.x] += red[threadIdx.x + st];
        __syncthreads();
    }
    if (threadIdx.x == 0) out[row] = red[0];
}

// ---------------- fp32 tiled GEMM: C[M,N] = A[M,K] * B[N,K]^T + epilogue ----
// EPI 0: logits  v = -2*sqrt(max(x2[m] + w2[n] - 2c, 1e-12))   (aux0=x2, aux1=w2)
// EPI 1: relu    v = max(c + bias[n], 0)                        (aux0=bias)
// EPI 2: bias    v = c + bias[n]                                (aux0=bias)
template<int EPI>
__global__ __launch_bounds__(256, 2)
void gemm128_kernel(const float* __restrict__ A, const float* __restrict__ Bm,
                    float* __restrict__ C, int N, int K,
                    const float* __restrict__ aux0, const float* __restrict__ aux1)
{
    __shared__ float As[32][132];   // [k][m], padded
    __shared__ float Bs[32][132];   // [k][n], padded

    const int bm = blockIdx.y * 128;
    const int bn = blockIdx.x * 128;
    const int tid = threadIdx.x;
    const int tx = tid & 15;        // n-group (8 cols each)
    const int ty = tid >> 4;        // m-group (8 rows each)
    const int lr = tid >> 3;        // 0..31 load row base
    const int lc = (tid & 7) << 2;  // k offset (float4)

    float acc[8][8];
#pragma unroll
    for (int i = 0; i < 8; i++)
#pragma unroll
        for (int j = 0; j < 8; j++) acc[i][j] = 0.f;

    for (int k0 = 0; k0 < K; k0 += 32) {
#pragma unroll
        for (int rr = 0; rr < 4; rr++) {
            int row = lr + rr * 32;
            float4 va = *(const float4*)&A[(size_t)(bm + row) * K + k0 + lc];
            As[lc + 0][row] = va.x; As[lc + 1][row] = va.y;
            As[lc + 2][row] = va.z; As[lc + 3][row] = va.w;
            float4 vb = make_float4(0.f, 0.f, 0.f, 0.f);
            if (bn + row < N)
                vb = *(const float4*)&Bm[(size_t)(bn + row) * K + k0 + lc];
            Bs[lc + 0][row] = vb.x; Bs[lc + 1][row] = vb.y;
            Bs[lc + 2][row] = vb.z; Bs[lc + 3][row] = vb.w;
        }
        __syncthreads();
#pragma unroll
        for (int kk = 0; kk < 32; kk++) {
            float4 a0 = *(const float4*)&As[kk][ty * 8];
            float4 a1 = *(const float4*)&As[kk][ty * 8 + 4];
            float4 b0 = *(const float4*)&Bs[kk][tx * 8];
            float4 b1 = *(const float4*)&Bs[kk][tx * 8 + 4];
            float a[8] = {a0.x, a0.y, a0.z, a0.w, a1.x, a1.y, a1.z, a1.w};
            float b[8] = {b0.x, b0.y, b0.z, b0.w, b1.x, b1.y, b1.z, b1.w};
#pragma unroll
            for (int i = 0; i < 8; i++)
#pragma unroll
                for (int j = 0; j < 8; j++)
                    acc[i][j] = fmaf(a[i], b[j], acc[i][j]);
        }
        __syncthreads();
    }

#pragma unroll
    for (int i = 0; i < 8; i++) {
        int m = bm + ty * 8 + i;
#pragma unroll
        for (int j = 0; j < 8; j++) {
            int n = bn + tx * 8 + j;
            if (n >= N) continue;
            float c = acc[i][j];
            float v;
            if (EPI == 0) {
                float d2 = aux0[m] + aux1[n] - 2.f * c;
                v = -TEMP_INV * sqrtf(fmaxf(d2, 1e-12f));
            } else if (EPI == 1) {
                v = fmaxf(c + aux0[n], 0.f);
            } else {
                v = c + aux0[n];
            }
            C[(size_t)m * N + n] = v;
        }
    }
}

// ---------------- fused softmax (in place) + argmax(logit)=argmin(dist) ----
// One CTA per row; whole row (4096) held in registers (16/thread).
__global__ __launch_bounds__(256)
void softmax_argmax_kernel(float* __restrict__ S, float* __restrict__ winners)
{
    const int row = blockIdx.x;
    const int tid = threadIdx.x;
    float* p = S + (size_t)row * HDIM;

    float v[16];
    float best = -1e30f;
    int besti = HDIM;
#pragma unroll
    for (int t = 0; t < 16; t++) {
        int i = tid + t * 256;              // ascending within thread
        v[t] = p[i];
        if (v[t] > best) { best = v[t]; besti = i; }   // strict > keeps first
    }

    __shared__ float sv[256];
    __shared__ int   si[256];
    sv[tid] = best; si[tid] = besti;
    __syncthreads();
    for (int st = 128; st > 0; st >>= 1) {
        if (tid < st) {
            float ov = sv[tid + st]; int oi = si[tid + st];
            if (ov > sv[tid] || (ov == sv[tid] && oi < si[tid])) {
                sv[tid] = ov; si[tid] = oi;
            }
        }
        __syncthreads();
    }
    const float mx = sv[0];
    if (tid == 0) winners[row] = (float)si[0];
    __syncthreads();

    float s = 0.f;
#pragma unroll
    for (int t = 0; t < 16; t++) {
        v[t] = expf(v[t] - mx);
        s += v[t];
    }
    sv[tid] = s;
    __syncthreads();
    for (int st = 128; st > 0; st >>= 1) {
        if (tid < st) sv[tid] += sv[tid + st];
        __syncthreads();
    }
    const float inv = 1.f / sv[0];
#pragma unroll
    for (int t = 0; t < 16; t++)
        p[tid + t * 256] = v[t] * inv;
}

// ---------------- launcher --------------------------------------------------
extern "C" void kernel_launch(void* const* d_in, const int* in_sizes, int n_in,
                              void* d_out, int out_size)
{
    const float* x  = (const float*)d_in[0];
    const float* W  = (const float*)d_in[1];
    const float* w1 = (const float*)d_in[2];
    const float* b1 = (const float*)d_in[3];
    const float* w2 = (const float*)d_in[4];
    const float* b2 = (const float*)d_in[5];
    const float* w3 = (const float*)d_in[6];
    const float* b3 = (const float*)d_in[7];
    float* out = (float*)d_out;

    float *S, *h1, *h2, *x2, *wsq;
    cudaGetSymbolAddress((void**)&S,   g_S);
    cudaGetSymbolAddress((void**)&h1,  g_h1);
    cudaGetSymbolAddress((void**)&h2,  g_h2);
    cudaGetSymbolAddress((void**)&x2,  g_x2);
    cudaGetSymbolAddress((void**)&wsq, g_w2);

    // winners (as float) live in the last BROWS elements of d_out
    float* winners = out + (size_t)out_size - BROWS;

    rowsq_kernel<<<BROWS, 256>>>(x, x2, DIN);
    rowsq_kernel<<<HDIM, 256>>>(W, wsq, DIN);

    // logits S = -2*sqrt(x2 + w2 - 2*x@W^T)
    gemm128_kernel<0><<<dim3(HDIM / 128, BROWS / 128), 256>>>(
        x, W, S, HDIM, DIN, x2, wsq);

    softmax_argmax_kernel<<<BROWS, 256>>>(S, winners);

    // h1 = relu(soft @ w1^T + b1)
    gemm128_kernel<1><<<dim3(H1DIM / 128, BROWS / 128), 256>>>(
        S, w1, h1, H1DIM, HDIM, b1, nullptr);
    // h2 = relu(h1 @ w2^T + b2)
    gemm128_kernel<1><<<dim3(H2DIM / 128, BROWS / 128), 256>>>(
        h1, w2, h2, H2DIM, H1DIM, b2, nullptr);
    // out = h2 @ w3^T + b3   (N=1000, bounds-checked)
    gemm128_kernel<2><<<dim3((OUTD + 127) / 128, BROWS / 128), 256>>>(
        h2, w3, out, OUTD, H2DIM, b3, nullptr);
}

// round 6
// speedup vs baseline: 3.0715x; 3.0715x over previous
#include <cuda_runtime.h>
#include <cuda_fp16.h>
#include <math.h>
#include <stdint.h>

// Problem dims (fixed by dataset)
#define BROWS 4096
#define HDIM  4096
#define DIN   2048
#define H1DIM 2048
#define H2DIM 1024
#define OUTD  1000
#define TEMP_INV 2.0f     // 1/TEMPERATURE
#define XSCALE 2048.0f
#define WSCALE 64.0f
#define INV_SCALE (1.0f / (2048.0f * 64.0f))   // exact power of 2

// GEMM tiling (fp16 mma.sync m16n8k16)
#define STAGES 3
#define BM 128
#define BN 128
#define BK 32
#define PAD 8
#define LDT (BK + PAD)                        // 40 halves per smem row

// ---------------- scratch (static device globals; no allocs allowed) --------
__device__ float  g_S  [(size_t)BROWS * HDIM];   // fp32 logits
__device__ __half g_Sb [(size_t)BROWS * HDIM];   // fp16 softmax
__device__ __half g_h1 [(size_t)BROWS * H1DIM];
__device__ __half g_h2 [(size_t)BROWS * H2DIM];
__device__ __half g_xh [(size_t)BROWS * DIN];
__device__ __half g_xl [(size_t)BROWS * DIN];
__device__ __half g_Wh [(size_t)HDIM * DIN];
__device__ __half g_Wl [(size_t)HDIM * DIN];
__device__ __half g_w1h[(size_t)H1DIM * HDIM];
__device__ __half g_w2h[(size_t)H2DIM * H1DIM];
__device__ __half g_w3h[(size_t)OUTD * H2DIM];
__device__ float  g_x2[BROWS];
__device__ float  g_w2s[HDIM];

// ---------------- PTX helpers ------------------------------------------------
__device__ __forceinline__ uint32_t smem_u32(const void* p) {
    uint32_t a;
    asm("{ .reg .u64 t; cvta.to.shared.u64 t, %1; cvt.u32.u64 %0, t; }"
        : "=r"(a) : "l"(p));
    return a;
}
__device__ __forceinline__ void cpa16(uint32_t s, const void* g, int sz) {
    asm volatile("cp.async.cg.shared.global [%0], [%1], 16, %2;"
                 :: "r"(s), "l"(g), "r"(sz));
}
__device__ __forceinline__ void cpa_commit() {
    asm volatile("cp.async.commit_group;" ::: "memory");
}
__device__ __forceinline__ void ldm_x4(uint32_t& r0, uint32_t& r1,
                                       uint32_t& r2, uint32_t& r3, uint32_t addr) {
    asm volatile("ldmatrix.sync.aligned.m8n8.x4.shared.b16 {%0,%1,%2,%3}, [%4];"
                 : "=r"(r0), "=r"(r1), "=r"(r2), "=r"(r3) : "r"(addr));
}
__device__ __forceinline__ void mma16816(float* c, const uint32_t* a, const uint32_t* b) {
    asm volatile(
        "mma.sync.aligned.m16n8k16.row.col.f32.f16.f16.f32 "
        "{%0,%1,%2,%3}, {%4,%5,%6,%7}, {%8,%9}, {%0,%1,%2,%3};"
        : "+f"(c[0]), "+f"(c[1]), "+f"(c[2]), "+f"(c[3])
        : "r"(a[0]), "r"(a[1]), "r"(a[2]), "r"(a[3]), "r"(b[0]), "r"(b[1]));
}

// ---------------- conversion kernels -----------------------------------------
// split: hi = rn(x*scale); lo = rn(x*scale - hi)   (both normal-range fp16)
__global__ void split_kernel(const float4* __restrict__ src,
                             uint2* __restrict__ hi4, uint2* __restrict__ lo4,
                             float scale, int n4)
{
    int i = blockIdx.x * 256 + threadIdx.x;
    if (i >= n4) return;
    float4 v = src[i];
    float s0 = v.x * scale, s1 = v.y * scale, s2 = v.z * scale, s3 = v.w * scale;
    __half h0 = __float2half_rn(s0), h1 = __float2half_rn(s1);
    __half h2 = __float2half_rn(s2), h3 = __float2half_rn(s3);
    __half l0 = __float2half_rn(s0 - __half2float(h0));
    __half l1 = __float2half_rn(s1 - __half2float(h1));
    __half l2 = __float2half_rn(s2 - __half2float(h2));
    __half l3 = __float2half_rn(s3 - __half2float(h3));
    __half2 ha = __halves2half2(h0, h1), hb = __halves2half2(h2, h3);
    __half2 la = __halves2half2(l0, l1), lb = __halves2half2(l2, l3);
    uint2 ho, lo;
    ho.x = *(const uint32_t*)&ha; ho.y = *(const uint32_t*)&hb;
    lo.x = *(const uint32_t*)&la; lo.y = *(const uint32_t*)&lb;
    hi4[i] = ho; lo4[i] = lo;
}

__global__ void f2h_kernel(const float4* __restrict__ src, uint2* __restrict__ dst, int n4)
{
    int i = blockIdx.x * 256 + threadIdx.x;
    if (i >= n4) return;
    float4 v = src[i];
    __half2 a = __halves2half2(__float2half_rn(v.x), __float2half_rn(v.y));
    __half2 b = __halves2half2(__float2half_rn(v.z), __float2half_rn(v.w));
    uint2 o;
    o.x = *(const uint32_t*)&a; o.y = *(const uint32_t*)&b;
    dst[i] = o;
}

// ---------------- row sum-of-squares (x rows then W rows, one grid) ---------
__global__ void rowsq_kernel(const float* __restrict__ X, const float* __restrict__ W,
                             float* __restrict__ ox, float* __restrict__ ow)
{
    int row = blockIdx.x;
    const float* p;
    float* o;
    if (row < BROWS) { p = X + (size_t)row * DIN; o = ox + row; }
    else             { p = W + (size_t)(row - BROWS) * DIN; o = ow + (row - BROWS); }
    float s = 0.f;
    for (int i = threadIdx.x; i < DIN; i += 256) {
        float v = p[i];
        s = fmaf(v, v, s);
    }
    __shared__ float red[256];
    red[threadIdx.x] = s;
    __syncthreads();
    for (int st = 128; st > 0; st >>= 1) {
        if (threadIdx.x < st) red[threadIdx.x] += red[threadIdx.x + st];
        __syncthreads();
    }
    if (threadIdx.x == 0) *o = red[0];
}

// ---------------- stage loader -----------------------------------------------
// Stage layout (halves): [Ah 128*LDT][Al if HILO][Bh 128*LDT][Bl if HILO]
template<int HILO>
__device__ __forceinline__ void load_tile(
    const __half* __restrict__ Ah, const __half* __restrict__ Al,
    const __half* __restrict__ Bh, const __half* __restrict__ Bl,
    int bm, int bn, int Nb, int K, int kt, int s, uint32_t sbase, int tid)
{
    const int TILES = HILO ? 4 : 2;
    uint32_t stg = sbase + (uint32_t)s * TILES * 128 * LDT * 2;
    const uint32_t aHi = stg;
    const uint32_t aLo = stg + 128 * LDT * 2;
    const uint32_t bHi = stg + (HILO ? 2 : 1) * 128 * LDT * 2;
    const uint32_t bLo = stg + 3 * 128 * LDT * 2;

    const size_t aoff = (size_t)bm * K + (size_t)kt * BK;
#pragma unroll
    for (int i = 0; i < 2; i++) {
        int c = tid + i * 256;
        int r = c >> 2, ch = c & 3;
        uint32_t so = (uint32_t)(r * LDT + ch * 8) * 2;
        size_t go = aoff + (size_t)r * K + ch * 8;
        cpa16(aHi + so, Ah + go, 16);
        if (HILO) cpa16(aLo + so, Al + go, 16);
    }
    const size_t boff = (size_t)kt * BK;
#pragma unroll
    for (int i = 0; i < 2; i++) {
        int c = tid + i * 256;
        int r = c >> 2, ch = c & 3;
        int grow = bn + r;
        int ok = (grow < Nb) ? 16 : 0;
        if (grow >= Nb) grow = Nb - 1;
        uint32_t so = (uint32_t)(r * LDT + ch * 8) * 2;
        size_t go = boff + (size_t)grow * K + ch * 8;
        cpa16(bHi + so, Bh + go, ok);
        if (HILO) cpa16(bLo + so, Bl + go, ok);
    }
}

// ---------------- fp16 mma.sync GEMM: C = A @ B^T + epilogue -----------------
// HILO=1: A=(Ah+Al), B=(Bh+Bl) split fp16; acc = ah*bh + ah*bl + al*bh (fp32-accurate)
// EPI 0: logits v = -2*sqrt(max(x2[m]+w2[n]-2*acc*INV_SCALE,1e-12)) -> float C
// EPI 1: relu   v = max(acc + bias[n], 0)  -> fp16 C
// EPI 2: bias   v = acc + bias[n]          -> float C
template<int EPI, int HILO>
__global__ __launch_bounds__(256)
void tc_gemm(const __half* __restrict__ Ah, const __half* __restrict__ Al,
             const __half* __restrict__ Bh, const __half* __restrict__ Bl,
             void* __restrict__ Cv, int Nb, int K,
             const float* __restrict__ aux0, const float* __restrict__ aux1)
{
    extern __shared__ char dsm[];
    const int tid  = threadIdx.x;
    const int wid  = tid >> 5;
    const int lane = tid & 31;
    const int wm   = wid & 3;        // 4 warp-rows of 32 m
    const int wn   = wid >> 2;       // 2 warp-cols of 64 n
    const int bm   = blockIdx.x * BM;
    const int bn   = blockIdx.y * BN;
    const uint32_t sbase = smem_u32(dsm);
    const int TILES = HILO ? 4 : 2;

    float acc[2][8][4];
#pragma unroll
    for (int mt = 0; mt < 2; mt++)
#pragma unroll
        for (int nt = 0; nt < 8; nt++)
#pragma unroll
            for (int i = 0; i < 4; i++) acc[mt][nt][i] = 0.f;

    const int T = K / BK;

    for (int p = 0; p < STAGES - 1; p++) {
        load_tile<HILO>(Ah, Al, Bh, Bl, bm, bn, Nb, K, p, p, sbase, tid);
        cpa_commit();
    }

    const int lrow = lane & 15;
    const int lcol = (lane >> 4) * 8;

    for (int t = 0; t < T; t++) {
        asm volatile("cp.async.wait_group %0;" :: "n"(STAGES - 2) : "memory");
        __syncthreads();

        int s = t % STAGES;
        uint32_t stg = sbase + (uint32_t)s * TILES * 128 * LDT * 2;
        const uint32_t aHi = stg;
        const uint32_t aLo = stg + 128 * LDT * 2;
        const uint32_t bHi = stg + (HILO ? 2 : 1) * 128 * LDT * 2;
        const uint32_t bLo = stg + 3 * 128 * LDT * 2;

#pragma unroll
        for (int ks = 0; ks < 2; ks++) {
            const uint32_t fo = (uint32_t)(ks * 16 + lcol) * 2;
            uint32_t ah[2][4], al[2][4];
#pragma unroll
            for (int mt = 0; mt < 2; mt++) {
                uint32_t ro = (uint32_t)((wm * 32 + mt * 16 + lrow) * LDT) * 2;
                ldm_x4(ah[mt][0], ah[mt][1], ah[mt][2], ah[mt][3], aHi + ro + fo);
                if (HILO)
                    ldm_x4(al[mt][0], al[mt][1], al[mt][2], al[mt][3], aLo + ro + fo);
            }
            uint32_t bh[8][2], bl[8][2];
#pragma unroll
            for (int np = 0; np < 4; np++) {
                uint32_t ro = (uint32_t)((wn * 64 + np * 16 + lrow) * LDT) * 2;
                uint32_t r0, r1, r2, r3;
                ldm_x4(r0, r1, r2, r3, bHi + ro + fo);
                bh[2*np][0] = r0; bh[2*np+1][0] = r1;
                bh[2*np][1] = r2; bh[2*np+1][1] = r3;
                if (HILO) {
                    ldm_x4(r0, r1, r2, r3, bLo + ro + fo);
                    bl[2*np][0] = r0; bl[2*np+1][0] = r1;
                    bl[2*np][1] = r2; bl[2*np+1][1] = r3;
                }
            }
#pragma unroll
            for (int mt = 0; mt < 2; mt++)
#pragma unroll
                for (int nt = 0; nt < 8; nt++) {
                    mma16816(acc[mt][nt], ah[mt], bh[nt]);
                    if (HILO) {
                        mma16816(acc[mt][nt], ah[mt], bl[nt]);
                        mma16816(acc[mt][nt], al[mt], bh[nt]);
                    }
                }
        }
        __syncthreads();

        int tn = t + STAGES - 1;
        if (tn < T)
            load_tile<HILO>(Ah, Al, Bh, Bl, bm, bn, Nb, K, tn, tn % STAGES, sbase, tid);
        cpa_commit();
    }

    const int r0 = lane >> 2;
    const int c0 = (lane & 3) * 2;
#pragma unroll
    for (int mt = 0; mt < 2; mt++) {
#pragma unroll
        for (int nt = 0; nt < 8; nt++) {
#pragma unroll
            for (int half = 0; half < 2; half++) {
                int m = bm + wm * 32 + mt * 16 + r0 + half * 8;
#pragma unroll
                for (int e = 0; e < 2; e++) {
                    int n = bn + wn * 64 + nt * 8 + c0 + e;
                    if (n >= Nb) continue;
                    float v = acc[mt][nt][half * 2 + e];
                    if (EPI == 0) {
                        float d2 = aux0[m] + aux1[n] - 2.f * (v * INV_SCALE);
                        ((float*)Cv)[(size_t)m * Nb + n] =
                            -TEMP_INV * sqrtf(fmaxf(d2, 1e-12f));
                    } else if (EPI == 1) {
                        ((__half*)Cv)[(size_t)m * Nb + n] =
                            __float2half_rn(fmaxf(v + aux0[n], 0.f));
                    } else {
                        ((float*)Cv)[(size_t)m * Nb + n] = v + aux0[n];
                    }
                }
            }
        }
    }
}

// ---------------- softmax + argmax (R1's exact passing logic) ---------------
__global__ __launch_bounds__(256)
void softmax_argmax_kernel(const float* __restrict__ S, __half* __restrict__ Sb,
                           float* __restrict__ winners)
{
    const int row = blockIdx.x;
    const int tid = threadIdx.x;
    const float* p = S + (size_t)row * HDIM;

    float v[16];
    float best = -1e30f;
    int besti = HDIM;
#pragma unroll
    for (int t = 0; t < 16; t++) {
        int i = tid + t * 256;               // ascending within thread
        v[t] = p[i];
        if (v[t] > best) { best = v[t]; besti = i; }   // strict > keeps first
    }

    __shared__ float sv[256];
    __shared__ int   si[256];
    sv[tid] = best; si[tid] = besti;
    __syncthreads();
    for (int st = 128; st > 0; st >>= 1) {
        if (tid < st) {
            float ov = sv[tid + st]; int oi = si[tid + st];
            if (ov > sv[tid] || (ov == sv[tid] && oi < si[tid])) {
                sv[tid] = ov; si[tid] = oi;
            }
        }
        __syncthreads();
    }
    const float mx = sv[0];
    if (tid == 0) winners[row] = (float)si[0];
    __syncthreads();

    float s = 0.f;
#pragma unroll
    for (int t = 0; t < 16; t++) {
        v[t] = expf(v[t] - mx);
        s += v[t];
    }
    sv[tid] = s;
    __syncthreads();
    for (int st = 128; st > 0; st >>= 1) {
        if (tid < st) sv[tid] += sv[tid + st];
        __syncthreads();
    }
    const float inv = 1.f / sv[0];
    __half* ob = Sb + (size_t)row * HDIM;
#pragma unroll
    for (int t = 0; t < 16; t++)
        ob[tid + t * 256] = __float2half_rn(v[t] * inv);
}

// ---------------- launcher --------------------------------------------------
extern "C" void kernel_launch(void* const* d_in, const int* in_sizes, int n_in,
                              void* d_out, int out_size)
{
    const float* x  = (const float*)d_in[0];
    const float* W  = (const float*)d_in[1];
    const float* w1 = (const float*)d_in[2];
    const float* b1 = (const float*)d_in[3];
    const float* w2 = (const float*)d_in[4];
    const float* b2 = (const float*)d_in[5];
    const float* w3 = (const float*)d_in[6];
    const float* b3 = (const float*)d_in[7];
    float* out = (float*)d_out;

    float *S, *x2, *wsq;
    __half *Sb, *h1, *h2, *xh, *xl, *Wh, *Wl, *w1h, *w2h, *w3h;
    cudaGetSymbolAddress((void**)&S,   g_S);
    cudaGetSymbolAddress((void**)&Sb,  g_Sb);
    cudaGetSymbolAddress((void**)&h1,  g_h1);
    cudaGetSymbolAddress((void**)&h2,  g_h2);
    cudaGetSymbolAddress((void**)&xh,  g_xh);
    cudaGetSymbolAddress((void**)&xl,  g_xl);
    cudaGetSymbolAddress((void**)&Wh,  g_Wh);
    cudaGetSymbolAddress((void**)&Wl,  g_Wl);
    cudaGetSymbolAddress((void**)&w1h, g_w1h);
    cudaGetSymbolAddress((void**)&w2h, g_w2h);
    cudaGetSymbolAddress((void**)&w3h, g_w3h);
    cudaGetSymbolAddress((void**)&x2,  g_x2);
    cudaGetSymbolAddress((void**)&wsq, g_w2s);

    const int SMEM_HILO = STAGES * 4 * 128 * LDT * 2;   // 122880
    const int SMEM_STD  = STAGES * 2 * 128 * LDT * 2;   // 61440
    cudaFuncSetAttribute(tc_gemm<0,1>, cudaFuncAttributeMaxDynamicSharedMemorySize, SMEM_HILO);
    cudaFuncSetAttribute(tc_gemm<1,0>, cudaFuncAttributeMaxDynamicSharedMemorySize, SMEM_STD);
    cudaFuncSetAttribute(tc_gemm<2,0>, cudaFuncAttributeMaxDynamicSharedMemorySize, SMEM_STD);

    float* winners = out + (size_t)out_size - BROWS;

    // conversions
    {
        int n4 = BROWS * DIN / 4;
        split_kernel<<<(n4 + 255) / 256, 256>>>((const float4*)x, (uint2*)xh, (uint2*)xl, XSCALE, n4);
    }
    {
        int n4 = HDIM * DIN / 4;
        split_kernel<<<(n4 + 255) / 256, 256>>>((const float4*)W, (uint2*)Wh, (uint2*)Wl, WSCALE, n4);
    }
    auto conv = [](const float* s, __half* d, size_t n) {
        int n4 = (int)(n / 4);
        f2h_kernel<<<(n4 + 255) / 256, 256>>>((const float4*)s, (uint2*)d, n4);
    };
    conv(w1, w1h, (size_t)H1DIM * HDIM);
    conv(w2, w2h, (size_t)H2DIM * H1DIM);
    conv(w3, w3h, (size_t)OUTD * H2DIM);

    rowsq_kernel<<<BROWS + HDIM, 256>>>(x, W, x2, wsq);

    // logits: fp16x3 split GEMM (fp32-accurate dot) + distance epilogue
    tc_gemm<0,1><<<dim3(BROWS / BM, HDIM / BN), 256, SMEM_HILO>>>(
        xh, xl, Wh, Wl, S, HDIM, DIN, x2, wsq);

    // softmax + exact argmax winners (R1 logic)
    softmax_argmax_kernel<<<BROWS, 256>>>(S, Sb, winners);

    // MLP in single fp16
    tc_gemm<1,0><<<dim3(BROWS / BM, H1DIM / BN), 256, SMEM_STD>>>(
        Sb, nullptr, w1h, nullptr, h1, H1DIM, HDIM, b1, nullptr);
    tc_gemm<1,0><<<dim3(BROWS / BM, H2DIM / BN), 256, SMEM_STD>>>(
        h1, nullptr, w2h, nullptr, h2, H2DIM, H1DIM, b2, nullptr);
    tc_gemm<2,0><<<dim3(BROWS / BM, (OUTD + BN - 1) / BN), 256, SMEM_STD>>>(
        h2, nullptr, w3h, nullptr, out, OUTD, H2DIM, b3, nullptr);
}

// round 7
// speedup vs baseline: 3.3429x; 1.0884x over previous
#include <cuda_runtime.h>
#include <cuda_fp16.h>
#include <math.h>
#include <stdint.h>

// Problem dims (fixed by dataset)
#define BROWS 4096
#define HDIM  4096
#define DIN   2048
#define H1DIM 2048
#define H2DIM 1024
#define OUTD  1000
#define TEMP_INV 2.0f     // 1/TEMPERATURE
#define XSCALE 2048.0f
#define WSCALE 64.0f
#define INV_SCALE (1.0f / (2048.0f * 64.0f))   // exact power of 2

// GEMM tiling (fp16 mma.sync m16n8k16)
#define BM 128
#define BN 128
#define BK 64
#define PAD 8
#define LDT (BK + PAD)                       // 72 halves per smem row (144 B)
#define TILE_B (128 * LDT * 2)               // one 128-row tile: 18432 B

// ---------------- scratch (static device globals; no allocs allowed) --------
__device__ float  g_S  [(size_t)BROWS * HDIM];   // fp32 logits
__device__ __half g_Sb [(size_t)BROWS * HDIM];   // fp16 softmax
__device__ __half g_h1 [(size_t)BROWS * H1DIM];
__device__ __half g_h2 [(size_t)BROWS * H2DIM];
__device__ __half g_xh [(size_t)BROWS * DIN];
__device__ __half g_xl [(size_t)BROWS * DIN];
__device__ __half g_Wh [(size_t)HDIM * DIN];
__device__ __half g_Wl [(size_t)HDIM * DIN];
__device__ __half g_w1h[(size_t)H1DIM * HDIM];
__device__ __half g_w2h[(size_t)H2DIM * H1DIM];
__device__ __half g_w3h[(size_t)OUTD * H2DIM];
__device__ float  g_x2[BROWS];
__device__ float  g_w2s[HDIM];

// ---------------- PTX helpers ------------------------------------------------
__device__ __forceinline__ uint32_t smem_u32(const void* p) {
    uint32_t a;
    asm("{ .reg .u64 t; cvta.to.shared.u64 t, %1; cvt.u32.u64 %0, t; }"
        : "=r"(a) : "l"(p));
    return a;
}
__device__ __forceinline__ void cpa16(uint32_t s, const void* g, int sz) {
    asm volatile("cp.async.cg.shared.global [%0], [%1], 16, %2;"
                 :: "r"(s), "l"(g), "r"(sz));
}
__device__ __forceinline__ void cpa_commit() {
    asm volatile("cp.async.commit_group;" ::: "memory");
}
__device__ __forceinline__ void ldm_x4(uint32_t& r0, uint32_t& r1,
                                       uint32_t& r2, uint32_t& r3, uint32_t addr) {
    asm volatile("ldmatrix.sync.aligned.m8n8.x4.shared.b16 {%0,%1,%2,%3}, [%4];"
                 : "=r"(r0), "=r"(r1), "=r"(r2), "=r"(r3) : "r"(addr));
}
__device__ __forceinline__ void mma16816(float* c, const uint32_t* a, const uint32_t* b) {
    asm volatile(
        "mma.sync.aligned.m16n8k16.row.col.f32.f16.f16.f32 "
        "{%0,%1,%2,%3}, {%4,%5,%6,%7}, {%8,%9}, {%0,%1,%2,%3};"
        : "+f"(c[0]), "+f"(c[1]), "+f"(c[2]), "+f"(c[3])
        : "r"(a[0]), "r"(a[1]), "r"(a[2]), "r"(a[3]), "r"(b[0]), "r"(b[1]));
}

// ---------------- conversion kernels -----------------------------------------
__global__ void split_kernel(const float4* __restrict__ src,
                             uint2* __restrict__ hi4, uint2* __restrict__ lo4,
                             float scale, int n4)
{
    int i = blockIdx.x * 256 + threadIdx.x;
    if (i >= n4) return;
    float4 v = src[i];
    float s0 = v.x * scale, s1 = v.y * scale, s2 = v.z * scale, s3 = v.w * scale;
    __half h0 = __float2half_rn(s0), h1 = __float2half_rn(s1);
    __half h2 = __float2half_rn(s2), h3 = __float2half_rn(s3);
    __half l0 = __float2half_rn(s0 - __half2float(h0));
    __half l1 = __float2half_rn(s1 - __half2float(h1));
    __half l2 = __float2half_rn(s2 - __half2float(h2));
    __half l3 = __float2half_rn(s3 - __half2float(h3));
    __half2 ha = __halves2half2(h0, h1), hb = __halves2half2(h2, h3);
    __half2 la = __halves2half2(l0, l1), lb = __halves2half2(l2, l3);
    uint2 ho, lo;
    ho.x = *(const uint32_t*)&ha; ho.y = *(const uint32_t*)&hb;
    lo.x = *(const uint32_t*)&la; lo.y = *(const uint32_t*)&lb;
    hi4[i] = ho; lo4[i] = lo;
}

__global__ void f2h_kernel(const float4* __restrict__ src, uint2* __restrict__ dst, int n4)
{
    int i = blockIdx.x * 256 + threadIdx.x;
    if (i >= n4) return;
    float4 v = src[i];
    __half2 a = __halves2half2(__float2half_rn(v.x), __float2half_rn(v.y));
    __half2 b = __halves2half2(__float2half_rn(v.z), __float2half_rn(v.w));
    uint2 o;
    o.x = *(const uint32_t*)&a; o.y = *(const uint32_t*)&b;
    dst[i] = o;
}

// ---------------- row sum-of-squares (x rows then W rows, one grid) ---------
__global__ void rowsq_kernel(const float* __restrict__ X, const float* __restrict__ W,
                             float* __restrict__ ox, float* __restrict__ ow)
{
    int row = blockIdx.x;
    const float* p;
    float* o;
    if (row < BROWS) { p = X + (size_t)row * DIN; o = ox + row; }
    else             { p = W + (size_t)(row - BROWS) * DIN; o = ow + (row - BROWS); }
    float s = 0.f;
    for (int i = threadIdx.x; i < DIN; i += 256) {
        float v = p[i];
        s = fmaf(v, v, s);
    }
    __shared__ float red[256];
    red[threadIdx.x] = s;
    __syncthreads();
    for (int st = 128; st > 0; st >>= 1) {
        if (threadIdx.x < st) red[threadIdx.x] += red[threadIdx.x + st];
        __syncthreads();
    }
    if (threadIdx.x == 0) *o = red[0];
}

// ---------------- stage loader -----------------------------------------------
// Stage layout (tiles of 128 rows x LDT halves): [Ah][Al?][Bh][Bl?]
template<int HILO>
__device__ __forceinline__ void load_tile(
    const __half* __restrict__ Ah, const __half* __restrict__ Al,
    const __half* __restrict__ Bh, const __half* __restrict__ Bl,
    int bm, int bn, int Nb, int K, int kt, int s, uint32_t sbase, int tid)
{
    const int TILES = HILO ? 4 : 2;
    uint32_t stg = sbase + (uint32_t)s * TILES * TILE_B;
    const uint32_t aHi = stg;
    const uint32_t aLo = stg + TILE_B;
    const uint32_t bHi = stg + (HILO ? 2 : 1) * TILE_B;
    const uint32_t bLo = stg + 3 * TILE_B;

    const size_t aoff = (size_t)bm * K + (size_t)kt * BK;
#pragma unroll
    for (int i = 0; i < 4; i++) {               // 1024 chunks / 256 threads
        int c = tid + i * 256;
        int r = c >> 3, ch = c & 7;             // 8 x 16B chunks per 128B row
        uint32_t so = (uint32_t)(r * LDT + ch * 8) * 2;
        size_t go = aoff + (size_t)r * K + ch * 8;
        cpa16(aHi + so, Ah + go, 16);
        if (HILO) cpa16(aLo + so, Al + go, 16);
    }
    const size_t boff = (size_t)kt * BK;
#pragma unroll
    for (int i = 0; i < 4; i++) {
        int c = tid + i * 256;
        int r = c >> 3, ch = c & 7;
        int grow = bn + r;
        int ok = (grow < Nb) ? 16 : 0;
        if (grow >= Nb) grow = Nb - 1;
        uint32_t so = (uint32_t)(r * LDT + ch * 8) * 2;
        size_t go = boff + (size_t)grow * K + ch * 8;
        cpa16(bHi + so, Bh + go, ok);
        if (HILO) cpa16(bLo + so, Bl + go, ok);
    }
}

// ---------------- fp16 mma.sync GEMM: C = A @ B^T + epilogue -----------------
// HILO=1: split operands; acc = ah*bh + ah*bl + al*bh (fp32-accurate)
// EPI 0: logits -> float C;  EPI 1: relu+bias -> fp16 C;  EPI 2: bias -> float C
template<int EPI, int HILO, int STG>
__global__ __launch_bounds__(256)
void tc_gemm(const __half* __restrict__ Ah, const __half* __restrict__ Al,
             const __half* __restrict__ Bh, const __half* __restrict__ Bl,
             void* __restrict__ Cv, int Nb, int K,
             const float* __restrict__ aux0, const float* __restrict__ aux1)
{
    extern __shared__ char dsm[];
    const int tid  = threadIdx.x;
    const int wid  = tid >> 5;
    const int lane = tid & 31;
    const int wm   = wid & 3;        // 4 warp-rows of 32 m
    const int wn   = wid >> 2;       // 2 warp-cols of 64 n
    const int bm   = blockIdx.x * BM;
    const int bn   = blockIdx.y * BN;
    const uint32_t sbase = smem_u32(dsm);
    const int TILES = HILO ? 4 : 2;

    float acc[2][8][4];
#pragma unroll
    for (int mt = 0; mt < 2; mt++)
#pragma unroll
        for (int nt = 0; nt < 8; nt++)
#pragma unroll
            for (int i = 0; i < 4; i++) acc[mt][nt][i] = 0.f;

    const int T = K / BK;
    const int lrow = lane & 15;
    const int lcol = (lane >> 4) * 8;

    // prologue: issue STG-1 stages
#pragma unroll
    for (int p = 0; p < STG - 1; p++) {
        load_tile<HILO>(Ah, Al, Bh, Bl, bm, bn, Nb, K, p, p, sbase, tid);
        cpa_commit();
    }

    // fragment double buffers (ks-level)
    uint32_t ah[2][2][4], al[2][2][4];
    uint32_t bh[2][8][2], bl[2][8][2];

    for (int t = 0; t < T; t++) {
        asm volatile("cp.async.wait_group %0;" :: "n"(STG - 2) : "memory");
        __syncthreads();

        // issue next tile BEFORE compute so loads overlap the MMAs below
        int tn = t + STG - 1;
        if (tn < T)
            load_tile<HILO>(Ah, Al, Bh, Bl, bm, bn, Nb, K, tn, tn % STG, sbase, tid);
        cpa_commit();

        int s = t % STG;
        uint32_t stg = sbase + (uint32_t)s * TILES * TILE_B;
        const uint32_t aHi = stg;
        const uint32_t aLo = stg + TILE_B;
        const uint32_t bHi = stg + (HILO ? 2 : 1) * TILE_B;
        const uint32_t bLo = stg + 3 * TILE_B;

        // per-warp row byte offsets
        uint32_t aro[2], bro[4];
#pragma unroll
        for (int mt = 0; mt < 2; mt++)
            aro[mt] = (uint32_t)((wm * 32 + mt * 16 + lrow) * LDT) * 2;
#pragma unroll
        for (int np = 0; np < 4; np++)
            bro[np] = (uint32_t)((wn * 64 + np * 16 + lrow) * LDT) * 2;

        // frag loader for one ks into buffer bu
        auto ldfr = [&](int bu, int ks) {
            uint32_t fo = (uint32_t)(ks * 16 + lcol) * 2;
#pragma unroll
            for (int mt = 0; mt < 2; mt++) {
                ldm_x4(ah[bu][mt][0], ah[bu][mt][1], ah[bu][mt][2], ah[bu][mt][3],
                       aHi + aro[mt] + fo);
                if (HILO)
                    ldm_x4(al[bu][mt][0], al[bu][mt][1], al[bu][mt][2], al[bu][mt][3],
                           aLo + aro[mt] + fo);
            }
#pragma unroll
            for (int np = 0; np < 4; np++) {
                uint32_t r0, r1, r2, r3;
                ldm_x4(r0, r1, r2, r3, bHi + bro[np] + fo);
                bh[bu][2*np][0] = r0; bh[bu][2*np+1][0] = r1;
                bh[bu][2*np][1] = r2; bh[bu][2*np+1][1] = r3;
                if (HILO) {
                    ldm_x4(r0, r1, r2, r3, bLo + bro[np] + fo);
                    bl[bu][2*np][0] = r0; bl[bu][2*np+1][0] = r1;
                    bl[bu][2*np][1] = r2; bl[bu][2*np+1][1] = r3;
                }
            }
        };

        ldfr(0, 0);
#pragma unroll
        for (int ks = 0; ks < BK / 16; ks++) {
            int cur = ks & 1;
            if (ks + 1 < BK / 16) ldfr(cur ^ 1, ks + 1);   // prefetch next frags
#pragma unroll
            for (int mt = 0; mt < 2; mt++)
#pragma unroll
                for (int nt = 0; nt < 8; nt++) {
                    mma16816(acc[mt][nt], ah[cur][mt], bh[cur][nt]);
                    if (HILO) {
                        mma16816(acc[mt][nt], ah[cur][mt], bl[cur][nt]);
                        mma16816(acc[mt][nt], al[cur][mt], bh[cur][nt]);
                    }
                }
        }
    }

    // ---- epilogue ----
    const int r0 = lane >> 2;
    const int c0 = (lane & 3) * 2;
#pragma unroll
    for (int mt = 0; mt < 2; mt++) {
#pragma unroll
        for (int nt = 0; nt < 8; nt++) {
#pragma unroll
            for (int half = 0; half < 2; half++) {
                int m = bm + wm * 32 + mt * 16 + r0 + half * 8;
#pragma unroll
                for (int e = 0; e < 2; e++) {
                    int n = bn + wn * 64 + nt * 8 + c0 + e;
                    if (n >= Nb) continue;
                    float v = acc[mt][nt][half * 2 + e];
                    if (EPI == 0) {
                        float d2 = aux0[m] + aux1[n] - 2.f * (v * INV_SCALE);
                        ((float*)Cv)[(size_t)m * Nb + n] =
                            -TEMP_INV * sqrtf(fmaxf(d2, 1e-12f));
                    } else if (EPI == 1) {
                        ((__half*)Cv)[(size_t)m * Nb + n] =
                            __float2half_rn(fmaxf(v + aux0[n], 0.f));
                    } else {
                        ((float*)Cv)[(size_t)m * Nb + n] = v + aux0[n];
                    }
                }
            }
        }
    }
}

// ---------------- softmax + argmax (exact fp32 logits) -----------------------
__global__ __launch_bounds__(256)
void softmax_argmax_kernel(const float* __restrict__ S, __half* __restrict__ Sb,
                           float* __restrict__ winners)
{
    const int row = blockIdx.x;
    const int tid = threadIdx.x;
    const float* p = S + (size_t)row * HDIM;

    float v[16];
    float best = -1e30f;
    int besti = HDIM;
#pragma unroll
    for (int t = 0; t < 16; t++) {
        int i = tid + t * 256;               // ascending within thread
        v[t] = p[i];
        if (v[t] > best) { best = v[t]; besti = i; }   // strict > keeps first
    }

    __shared__ float sv[256];
    __shared__ int   si[256];
    sv[tid] = best; si[tid] = besti;
    __syncthreads();
    for (int st = 128; st > 0; st >>= 1) {
        if (tid < st) {
            float ov = sv[tid + st]; int oi = si[tid + st];
            if (ov > sv[tid] || (ov == sv[tid] && oi < si[tid])) {
                sv[tid] = ov; si[tid] = oi;
            }
        }
        __syncthreads();
    }
    const float mx = sv[0];
    if (tid == 0) winners[row] = (float)si[0];
    __syncthreads();

    float s = 0.f;
#pragma unroll
    for (int t = 0; t < 16; t++) {
        v[t] = expf(v[t] - mx);
        s += v[t];
    }
    sv[tid] = s;
    __syncthreads();
    for (int st = 128; st > 0; st >>= 1) {
        if (tid < st) sv[tid] += sv[tid + st];
        __syncthreads();
    }
    const float inv = 1.f / sv[0];
    __half* ob = Sb + (size_t)row * HDIM;
#pragma unroll
    for (int t = 0; t < 16; t++)
        ob[tid + t * 256] = __float2half_rn(v[t] * inv);
}

// ---------------- launcher --------------------------------------------------
extern "C" void kernel_launch(void* const* d_in, const int* in_sizes, int n_in,
                              void* d_out, int out_size)
{
    const float* x  = (const float*)d_in[0];
    const float* W  = (const float*)d_in[1];
    const float* w1 = (const float*)d_in[2];
    const float* b1 = (const float*)d_in[3];
    const float* w2 = (const float*)d_in[4];
    const float* b2 = (const float*)d_in[5];
    const float* w3 = (const float*)d_in[6];
    const float* b3 = (const float*)d_in[7];
    float* out = (float*)d_out;

    float *S, *x2, *wsq;
    __half *Sb, *h1, *h2, *xh, *xl, *Wh, *Wl, *w1h, *w2h, *w3h;
    cudaGetSymbolAddress((void**)&S,   g_S);
    cudaGetSymbolAddress((void**)&Sb,  g_Sb);
    cudaGetSymbolAddress((void**)&h1,  g_h1);
    cudaGetSymbolAddress((void**)&h2,  g_h2);
    cudaGetSymbolAddress((void**)&xh,  g_xh);
    cudaGetSymbolAddress((void**)&xl,  g_xl);
    cudaGetSymbolAddress((void**)&Wh,  g_Wh);
    cudaGetSymbolAddress((void**)&Wl,  g_Wl);
    cudaGetSymbolAddress((void**)&w1h, g_w1h);
    cudaGetSymbolAddress((void**)&w2h, g_w2h);
    cudaGetSymbolAddress((void**)&w3h, g_w3h);
    cudaGetSymbolAddress((void**)&x2,  g_x2);
    cudaGetSymbolAddress((void**)&wsq, g_w2s);

    const int SMEM_HILO = 2 * 4 * TILE_B;   // 2 stages x 4 tiles = 147456 B
    const int SMEM_STD  = 3 * 2 * TILE_B;   // 3 stages x 2 tiles = 110592 B
    cudaFuncSetAttribute(tc_gemm<0,1,2>, cudaFuncAttributeMaxDynamicSharedMemorySize, SMEM_HILO);
    cudaFuncSetAttribute(tc_gemm<1,0,3>, cudaFuncAttributeMaxDynamicSharedMemorySize, SMEM_STD);
    cudaFuncSetAttribute(tc_gemm<2,0,3>, cudaFuncAttributeMaxDynamicSharedMemorySize, SMEM_STD);

    float* winners = out + (size_t)out_size - BROWS;

    // conversions
    {
        int n4 = BROWS * DIN / 4;
        split_kernel<<<(n4 + 255) / 256, 256>>>((const float4*)x, (uint2*)xh, (uint2*)xl, XSCALE, n4);
    }
    {
        int n4 = HDIM * DIN / 4;
        split_kernel<<<(n4 + 255) / 256, 256>>>((const float4*)W, (uint2*)Wh, (uint2*)Wl, WSCALE, n4);
    }
    auto conv = [](const float* s, __half* d, size_t n) {
        int n4 = (int)(n / 4);
        f2h_kernel<<<(n4 + 255) / 256, 256>>>((const float4*)s, (uint2*)d, n4);
    };
    conv(w1, w1h, (size_t)H1DIM * HDIM);
    conv(w2, w2h, (size_t)H2DIM * H1DIM);
    conv(w3, w3h, (size_t)OUTD * H2DIM);

    rowsq_kernel<<<BROWS + HDIM, 256>>>(x, W, x2, wsq);

    // logits: fp16x3 split GEMM (fp32-accurate dot) + distance epilogue
    tc_gemm<0,1,2><<<dim3(BROWS / BM, HDIM / BN), 256, SMEM_HILO>>>(
        xh, xl, Wh, Wl, S, HDIM, DIN, x2, wsq);

    // softmax + exact argmax winners
    softmax_argmax_kernel<<<BROWS, 256>>>(S, Sb, winners);

    // MLP in single fp16
    tc_gemm<1,0,3><<<dim3(BROWS / BM, H1DIM / BN), 256, SMEM_STD>>>(
        Sb, nullptr, w1h, nullptr, h1, H1DIM, HDIM, b1, nullptr);
    tc_gemm<1,0,3><<<dim3(BROWS / BM, H2DIM / BN), 256, SMEM_STD>>>(
        h1, nullptr, w2h, nullptr, h2, H2DIM, H1DIM, b2, nullptr);
    tc_gemm<2,0,3><<<dim3(BROWS / BM, (OUTD + BN - 1) / BN), 256, SMEM_STD>>>(
        h2, nullptr, w3h, nullptr, out, OUTD, H2DIM, b3, nullptr);
}

// round 10
// speedup vs baseline: 4.5056x; 1.3478x over previous
#include <cuda_runtime.h>
#include <cuda_fp16.h>
#include <math.h>
#include <stdint.h>

// Problem dims (fixed by dataset)
#define BROWS 4096
#define HDIM  4096
#define DIN   2048
#define H1DIM 2048
#define H2DIM 1024
#define OUTD  1000
#define TEMP_INV 2.0f       // 1/TEMPERATURE
#define XSCALE 32.0f
#define WSCALE 64.0f
#define INV_SCALE (1.0f / 2048.0f)   // 1/(XSCALE*WSCALE), exact power of 2
#define MARGIN 0.005f       // logit margin for winner recheck (~140 sigma of fp16 noise)

// GEMM tiling (fp16 mma.sync m16n8k16)
#define BM 128
#define BN 128
#define BK 64
#define PAD 8
#define LDT (BK + PAD)                       // 72 halves per smem row (144 B)
#define TILE_B (128 * LDT * 2)               // one 128-row tile: 18432 B
#define STG 3
#define SMEM_STD (STG * 2 * TILE_B)          // 110592 B

// ---------------- scratch (static device globals; no allocs allowed) --------
__device__ float  g_S  [(size_t)BROWS * HDIM];   // fp32 logits
__device__ __half g_Sb [(size_t)BROWS * HDIM];   // fp16 softmax
__device__ __half g_h1 [(size_t)BROWS * H1DIM];
__device__ __half g_h2 [(size_t)BROWS * H2DIM];
__device__ __half g_xh [(size_t)BROWS * DIN];
__device__ __half g_Wh [(size_t)HDIM * DIN];
__device__ __half g_w1h[(size_t)H1DIM * HDIM];
__device__ __half g_w2h[(size_t)H2DIM * H1DIM];
__device__ __half g_w3h[(size_t)OUTD * H2DIM];
__device__ float  g_x2[BROWS];
__device__ float  g_w2s[HDIM];

// ---------------- PTX helpers ------------------------------------------------
__device__ __forceinline__ uint32_t smem_u32(const void* p) {
    uint32_t a;
    asm("{ .reg .u64 t; cvta.to.shared.u64 t, %1; cvt.u32.u64 %0, t; }"
        : "=r"(a) : "l"(p));
    return a;
}
__device__ __forceinline__ void cpa16(uint32_t s, const void* g, int sz) {
    asm volatile("cp.async.cg.shared.global [%0], [%1], 16, %2;"
                 :: "r"(s), "l"(g), "r"(sz));
}
__device__ __forceinline__ void cpa_commit() {
    asm volatile("cp.async.commit_group;" ::: "memory");
}
__device__ __forceinline__ void ldm_x4(uint32_t& r0, uint32_t& r1,
                                       uint32_t& r2, uint32_t& r3, uint32_t addr) {
    asm volatile("ldmatrix.sync.aligned.m8n8.x4.shared.b16 {%0,%1,%2,%3}, [%4];"
                 : "=r"(r0), "=r"(r1), "=r"(r2), "=r"(r3) : "r"(addr));
}
__device__ __forceinline__ void mma16816(float* c, const uint32_t* a, const uint32_t* b) {
    asm volatile(
        "mma.sync.aligned.m16n8k16.row.col.f32.f16.f16.f32 "
        "{%0,%1,%2,%3}, {%4,%5,%6,%7}, {%8,%9}, {%0,%1,%2,%3};"
        : "+f"(c[0]), "+f"(c[1]), "+f"(c[2]), "+f"(c[3])
        : "r"(a[0]), "r"(a[1]), "r"(a[2]), "r"(a[3]), "r"(b[0]), "r"(b[1]));
}

// ---------------- conversion kernels -----------------------------------------
__global__ void f2hs_kernel(const float4* __restrict__ src, uint2* __restrict__ dst,
                            float scale, int n4)
{
    int i = blockIdx.x * 256 + threadIdx.x;
    if (i >= n4) return;
    float4 v = src[i];
    __half2 a = __halves2half2(__float2half_rn(v.x * scale), __float2half_rn(v.y * scale));
    __half2 b = __halves2half2(__float2half_rn(v.z * scale), __float2half_rn(v.w * scale));
    uint2 o;
    o.x = *(const uint32_t*)&a; o.y = *(const uint32_t*)&b;
    dst[i] = o;
}

// convert two arrays in one launch (keeps gemm0 at launch index 5 for ncu -s 5)
__global__ void f2h2_kernel(const float4* __restrict__ s0, uint2* __restrict__ d0, int n40,
                            const float4* __restrict__ s1, uint2* __restrict__ d1, int n41)
{
    int i = blockIdx.x * 256 + threadIdx.x;
    const float4* s; uint2* d;
    if (i < n40) { s = s0 + i; d = d0 + i; }
    else if (i < n40 + n41) { s = s1 + (i - n40); d = d1 + (i - n40); }
    else return;
    float4 v = *s;
    __half2 a = __halves2half2(__float2half_rn(v.x), __float2half_rn(v.y));
    __half2 b = __halves2half2(__float2half_rn(v.z), __float2half_rn(v.w));
    uint2 o;
    o.x = *(const uint32_t*)&a; o.y = *(const uint32_t*)&b;
    *d = o;
}

// ---------------- row sum-of-squares (x rows then W rows, one grid) ---------
__global__ void rowsq_kernel(const float* __restrict__ X, const float* __restrict__ W,
                             float* __restrict__ ox, float* __restrict__ ow)
{
    int row = blockIdx.x;
    const float* p;
    float* o;
    if (row < BROWS) { p = X + (size_t)row * DIN; o = ox + row; }
    else             { p = W + (size_t)(row - BROWS) * DIN; o = ow + (row - BROWS); }
    float s = 0.f;
    for (int i = threadIdx.x; i < DIN; i += 256) {
        float v = p[i];
        s = fmaf(v, v, s);
    }
    __shared__ float red[256];
    red[threadIdx.x] = s;
    __syncthreads();
    for (int st = 128; st > 0; st >>= 1) {
        if (threadIdx.x < st) red[threadIdx.x] += red[threadIdx.x + st];
        __syncthreads();
    }
    if (threadIdx.x == 0) *o = red[0];
}

// ---------------- stage loader -----------------------------------------------
__device__ __forceinline__ void load_tile(
    const __half* __restrict__ A, const __half* __restrict__ Bm,
    int bm, int bn, int Nb, int K, int kt, int s, uint32_t sbase, int tid)
{
    uint32_t stg = sbase + (uint32_t)s * 2 * TILE_B;
    const uint32_t aT = stg;
    const uint32_t bT = stg + TILE_B;

    const size_t aoff = (size_t)bm * K + (size_t)kt * BK;
#pragma unroll
    for (int i = 0; i < 4; i++) {               // 1024 chunks / 256 threads
        int c = tid + i * 256;
        int r = c >> 3, ch = c & 7;             // 8 x 16B chunks per 128B row
        cpa16(aT + (uint32_t)(r * LDT + ch * 8) * 2,
              A + aoff + (size_t)r * K + ch * 8, 16);
    }
    const size_t boff = (size_t)kt * BK;
#pragma unroll
    for (int i = 0; i < 4; i++) {
        int c = tid + i * 256;
        int r = c >> 3, ch = c & 7;
        int grow = bn + r;
        int ok = (grow < Nb) ? 16 : 0;
        if (grow >= Nb) grow = Nb - 1;
        cpa16(bT + (uint32_t)(r * LDT + ch * 8) * 2,
              Bm + boff + (size_t)grow * K + ch * 8, ok);
    }
}

// ---------------- fp16 mma.sync GEMM: C = A @ B^T + epilogue -----------------
// EPI 0: logits -> float C;  EPI 1: relu+bias -> fp16 C;  EPI 2: bias -> float C
template<int EPI>
__global__ __launch_bounds__(256)
void tc_gemm(const __half* __restrict__ A, const __half* __restrict__ Bm,
             void* __restrict__ Cv, int Nb, int K,
             const float* __restrict__ aux0, const float* __restrict__ aux1)
{
    extern __shared__ char dsm[];
    const int tid  = threadIdx.x;
    const int wid  = tid >> 5;
    const int lane = tid & 31;
    const int wm   = wid & 3;        // 4 warp-rows of 32 m
    const int wn   = wid >> 2;       // 2 warp-cols of 64 n
    const int bm   = blockIdx.x * BM;
    const int bn   = blockIdx.y * BN;
    const uint32_t sbase = smem_u32(dsm);

    float acc[2][8][4];
#pragma unroll
    for (int mt = 0; mt < 2; mt++)
#pragma unroll
        for (int nt = 0; nt < 8; nt++)
#pragma unroll
            for (int i = 0; i < 4; i++) acc[mt][nt][i] = 0.f;

    const int T = K / BK;
    const int lrow = lane & 15;
    const int lcol = (lane >> 4) * 8;

#pragma unroll
    for (int p = 0; p < STG - 1; p++) {
        load_tile(A, Bm, bm, bn, Nb, K, p, p, sbase, tid);
        cpa_commit();
    }

    uint32_t ah[2][2][4];            // [buf][mt][frag]
    uint32_t bh[2][8][2];            // [buf][nt][frag]

    for (int t = 0; t < T; t++) {
        asm volatile("cp.async.wait_group %0;" :: "n"(STG - 2) : "memory");
        __syncthreads();

        int tn = t + STG - 1;        // issue next tile before compute
        if (tn < T)
            load_tile(A, Bm, bm, bn, Nb, K, tn, tn % STG, sbase, tid);
        cpa_commit();

        int s = t % STG;
        uint32_t stg = sbase + (uint32_t)s * 2 * TILE_B;
        const uint32_t aT = stg;
        const uint32_t bT = stg + TILE_B;

        uint32_t aro[2], bro[4];
#pragma unroll
        for (int mt = 0; mt < 2; mt++)
            aro[mt] = (uint32_t)((wm * 32 + mt * 16 + lrow) * LDT) * 2;
#pragma unroll
        for (int np = 0; np < 4; np++)
            bro[np] = (uint32_t)((wn * 64 + np * 16 + lrow) * LDT) * 2;

        auto ldfr = [&](int bu, int ks) {
            uint32_t fo = (uint32_t)(ks * 16 + lcol) * 2;
#pragma unroll
            for (int mt = 0; mt < 2; mt++)
                ldm_x4(ah[bu][mt][0], ah[bu][mt][1], ah[bu][mt][2], ah[bu][mt][3],
                       aT + aro[mt] + fo);
#pragma unroll
            for (int np = 0; np < 4; np++) {
                uint32_t r0, r1, r2, r3;
                ldm_x4(r0, r1, r2, r3, bT + bro[np] + fo);
                bh[bu][2*np][0] = r0; bh[bu][2*np+1][0] = r1;
                bh[bu][2*np][1] = r2; bh[bu][2*np+1][1] = r3;
            }
        };

        ldfr(0, 0);
#pragma unroll
        for (int ks = 0; ks < BK / 16; ks++) {
            int cur = ks & 1;
            if (ks + 1 < BK / 16) ldfr(cur ^ 1, ks + 1);
#pragma unroll
            for (int mt = 0; mt < 2; mt++)
#pragma unroll
                for (int nt = 0; nt < 8; nt++)
                    mma16816(acc[mt][nt], ah[cur][mt], bh[cur][nt]);
        }
    }

    // ---- epilogue ----
    const int r0 = lane >> 2;
    const int c0 = (lane & 3) * 2;
#pragma unroll
    for (int mt = 0; mt < 2; mt++) {
#pragma unroll
        for (int nt = 0; nt < 8; nt++) {
#pragma unroll
            for (int half = 0; half < 2; half++) {
                int m = bm + wm * 32 + mt * 16 + r0 + half * 8;
#pragma unroll
                for (int e = 0; e < 2; e++) {
                    int n = bn + wn * 64 + nt * 8 + c0 + e;
                    if (n >= Nb) continue;
                    float v = acc[mt][nt][half * 2 + e];
                    if (EPI == 0) {
                        float d2 = aux0[m] + aux1[n] - 2.f * (v * INV_SCALE);
                        ((float*)Cv)[(size_t)m * Nb + n] =
                            -TEMP_INV * sqrtf(fmaxf(d2, 1e-12f));
                    } else if (EPI == 1) {
                        ((__half*)Cv)[(size_t)m * Nb + n] =
                            __float2half_rn(fmaxf(v + aux0[n], 0.f));
                    } else {
                        ((float*)Cv)[(size_t)m * Nb + n] = v + aux0[n];
                    }
                }
            }
        }
    }
}

// ---------------- softmax (fp16 out) + winner recheck ------------------------
// Exact fp32 d2 per candidate, then ranked by fp32 DISTANCE = sqrtf(d2) with
// lowest-index tie-break — the same (sqrt-collapsed) ordering the reference's
// argmin-over-distances uses. Comparing raw d2 instead (R5/R8/R9) broke ties
// the reference collapses, flipping the same ~4 rows every run.
__global__ __launch_bounds__(256)
void softmax_fix_kernel(const float* __restrict__ S, __half* __restrict__ Sb,
                        float* __restrict__ winners,
                        const float* __restrict__ x, const float* __restrict__ W,
                        const float* __restrict__ x2v, const float* __restrict__ w2v)
{
    const int row = blockIdx.x;
    const int tid = threadIdx.x;
    const float* p = S + (size_t)row * HDIM;

    __shared__ float sv[256];
    __shared__ int   cand[64];
    __shared__ int   nc;
    __shared__ float cds[64];
    __shared__ float xs[DIN];
    __shared__ float ws[4][DIN];

    float v[16];
    float best = -1e30f;
#pragma unroll
    for (int t = 0; t < 16; t++) {
        v[t] = p[tid + t * 256];
        best = fmaxf(best, v[t]);
    }
    sv[tid] = best;
    if (tid == 0) nc = 0;
    __syncthreads();
    for (int st = 128; st > 0; st >>= 1) {
        if (tid < st) sv[tid] = fmaxf(sv[tid], sv[tid + st]);
        __syncthreads();
    }
    const float mx = sv[0];
    __syncthreads();

    // --- candidates within MARGIN of the max logit ---
    const float thr = mx - MARGIN;
#pragma unroll
    for (int t = 0; t < 16; t++)
        if (v[t] >= thr) {
            int s2 = atomicAdd(&nc, 1);
            if (s2 < 64) cand[s2] = tid + t * 256;
        }
    // stage x row (coalesced)
    for (int k = tid; k < DIN; k += 256) xs[k] = x[(size_t)row * DIN + k];
    __syncthreads();
    const int ncl = nc < 64 ? nc : 64;

    // --- exact recheck: k-ascending fp32 chain -> DISTANCE (sqrt) ---
    for (int base = 0; base < ncl; base += 4) {
        int g = (ncl - base) < 4 ? (ncl - base) : 4;
        for (int j = 0; j < g; j++) {
            const float* wr = W + (size_t)cand[base + j] * DIN;
            for (int k = tid; k < DIN; k += 256) ws[j][k] = wr[k];
        }
        __syncthreads();
        if (tid < g) {
            float acc = 0.f;
#pragma unroll 8
            for (int k = 0; k < DIN; k++)
                acc = fmaf(xs[k], ws[tid][k], acc);
            float d2 = x2v[row] + w2v[cand[base + tid]] - 2.f * acc;
            cds[base + tid] = sqrtf(fmaxf(d2, 1e-12f));   // rank by fp32 distance
        }
        __syncthreads();
    }
    if (tid == 0) {
        float bd = 3.4e38f;
        int bidx = 0x7fffffff;
        for (int c = 0; c < ncl; c++) {
            float d = cds[c];
            int idx = cand[c];
            if (d < bd || (d == bd && idx < bidx)) { bd = d; bidx = idx; }
        }
        winners[row] = (float)bidx;
    }

    // --- softmax -> fp16 ---
    float s = 0.f;
#pragma unroll
    for (int t = 0; t < 16; t++) {
        v[t] = expf(v[t] - mx);
        s += v[t];
    }
    sv[tid] = s;
    __syncthreads();
    for (int st = 128; st > 0; st >>= 1) {
        if (tid < st) sv[tid] += sv[tid + st];
        __syncthreads();
    }
    const float inv = 1.f / sv[0];
    __half* ob = Sb + (size_t)row * HDIM;
#pragma unroll
    for (int t = 0; t < 16; t++)
        ob[tid + t * 256] = __float2half_rn(v[t] * inv);
}

// ---------------- launcher --------------------------------------------------
extern "C" void kernel_launch(void* const* d_in, const int* in_sizes, int n_in,
                              void* d_out, int out_size)
{
    const float* x  = (const float*)d_in[0];
    const float* W  = (const float*)d_in[1];
    const float* w1 = (const float*)d_in[2];
    const float* b1 = (const float*)d_in[3];
    const float* w2 = (const float*)d_in[4];
    const float* b2 = (const float*)d_in[5];
    const float* w3 = (const float*)d_in[6];
    const float* b3 = (const float*)d_in[7];
    float* out = (float*)d_out;

    float *S, *x2, *wsq;
    __half *Sb, *h1, *h2, *xh, *Wh, *w1h, *w2h, *w3h;
    cudaGetSymbolAddress((void**)&S,   g_S);
    cudaGetSymbolAddress((void**)&Sb,  g_Sb);
    cudaGetSymbolAddress((void**)&h1,  g_h1);
    cudaGetSymbolAddress((void**)&h2,  g_h2);
    cudaGetSymbolAddress((void**)&xh,  g_xh);
    cudaGetSymbolAddress((void**)&Wh,  g_Wh);
    cudaGetSymbolAddress((void**)&w1h, g_w1h);
    cudaGetSymbolAddress((void**)&w2h, g_w2h);
    cudaGetSymbolAddress((void**)&w3h, g_w3h);
    cudaGetSymbolAddress((void**)&x2,  g_x2);
    cudaGetSymbolAddress((void**)&wsq, g_w2s);

    cudaFuncSetAttribute(tc_gemm<0>, cudaFuncAttributeMaxDynamicSharedMemorySize, SMEM_STD);
    cudaFuncSetAttribute(tc_gemm<1>, cudaFuncAttributeMaxDynamicSharedMemorySize, SMEM_STD);
    cudaFuncSetAttribute(tc_gemm<2>, cudaFuncAttributeMaxDynamicSharedMemorySize, SMEM_STD);

    float* winners = out + (size_t)out_size - BROWS;

    // launches 0-4 (gemm0 lands at index 5 so ncu -s 5 profiles it)
    {
        int n4 = BROWS * DIN / 4;
        f2hs_kernel<<<(n4 + 255) / 256, 256>>>((const float4*)x, (uint2*)xh, XSCALE, n4);
    }
    {
        int n4 = HDIM * DIN / 4;
        f2hs_kernel<<<(n4 + 255) / 256, 256>>>((const float4*)W, (uint2*)Wh, WSCALE, n4);
    }
    {
        int n4 = H1DIM * HDIM / 4;
        f2hs_kernel<<<(n4 + 255) / 256, 256>>>((const float4*)w1, (uint2*)w1h, 1.0f, n4);
    }
    {
        int n40 = H2DIM * H1DIM / 4, n41 = OUTD * H2DIM / 4;
        f2h2_kernel<<<(n40 + n41 + 255) / 256, 256>>>(
            (const float4*)w2, (uint2*)w2h, n40, (const float4*)w3, (uint2*)w3h, n41);
    }
    rowsq_kernel<<<BROWS + HDIM, 256>>>(x, W, x2, wsq);

    // launch 5: logits = -2*sqrt(x2 + w2 - 2*(xh@Wh^T)/2048)   (single fp16 GEMM)
    tc_gemm<0><<<dim3(BROWS / BM, HDIM / BN), 256, SMEM_STD>>>(
        xh, Wh, S, HDIM, DIN, x2, wsq);

    // softmax + distance-ranked winner recheck
    softmax_fix_kernel<<<BROWS, 256>>>(S, Sb, winners, x, W, x2, wsq);

    // MLP in fp16
    tc_gemm<1><<<dim3(BROWS / BM, H1DIM / BN), 256, SMEM_STD>>>(
        Sb, w1h, h1, H1DIM, HDIM, b1, nullptr);
    tc_gemm<1><<<dim3(BROWS / BM, H2DIM / BN), 256, SMEM_STD>>>(
        h1, w2h, h2, H2DIM, H1DIM, b2, nullptr);
    tc_gemm<2><<<dim3(BROWS / BM, (OUTD + BN - 1) / BN), 256, SMEM_STD>>>(
        h2, w3h, out, OUTD, H2DIM, b3, nullptr);
}

// round 11
// speedup vs baseline: 4.6005x; 1.0211x over previous
#include <cuda_runtime.h>
#include <cuda_fp16.h>
#include <math.h>
#include <stdint.h>

// Problem dims (fixed by dataset)
#define BROWS 4096
#define HDIM  4096
#define DIN   2048
#define H1DIM 2048
#define H2DIM 1024
#define OUTD  1000
#define TEMP_INV 2.0f       // 1/TEMPERATURE
#define XSCALE 32.0f
#define WSCALE 64.0f
#define INV_SCALE (1.0f / 2048.0f)   // 1/(XSCALE*WSCALE), exact power of 2
#define MARGIN 0.005f       // logit margin for winner recheck (~140 sigma of fp16 noise)

// GEMM tiling (fp16 mma.sync m16n8k16)
#define BM 128
#define BN 128
#define BK 64
#define PAD 8
#define LDT (BK + PAD)                       // 72 halves per smem row (144 B)
#define TILE_B (128 * LDT * 2)               // one 128-row tile: 18432 B
#define STG 4
#define SMEM_STD (STG * 2 * TILE_B)          // 147456 B

// ---------------- scratch (static device globals; no allocs allowed) --------
__device__ float  g_S  [(size_t)BROWS * HDIM];   // fp32 logits
__device__ __half g_Sb [(size_t)BROWS * HDIM];   // fp16 softmax
__device__ __half g_h1 [(size_t)BROWS * H1DIM];
__device__ __half g_h2 [(size_t)BROWS * H2DIM];
__device__ __half g_xh [(size_t)BROWS * DIN];
__device__ __half g_Wh [(size_t)HDIM * DIN];
__device__ __half g_w1h[(size_t)H1DIM * HDIM];
__device__ __half g_w2h[(size_t)H2DIM * H1DIM];
__device__ __half g_w3h[(size_t)OUTD * H2DIM];
__device__ float  g_x2[BROWS];
__device__ float  g_w2s[HDIM];

// ---------------- PTX helpers ------------------------------------------------
__device__ __forceinline__ uint32_t smem_u32(const void* p) {
    uint32_t a;
    asm("{ .reg .u64 t; cvta.to.shared.u64 t, %1; cvt.u32.u64 %0, t; }"
        : "=r"(a) : "l"(p));
    return a;
}
__device__ __forceinline__ void cpa16(uint32_t s, const void* g, int sz) {
    asm volatile("cp.async.cg.shared.global [%0], [%1], 16, %2;"
                 :: "r"(s), "l"(g), "r"(sz));
}
__device__ __forceinline__ void cpa_commit() {
    asm volatile("cp.async.commit_group;" ::: "memory");
}
__device__ __forceinline__ void ldm_x4(uint32_t& r0, uint32_t& r1,
                                       uint32_t& r2, uint32_t& r3, uint32_t addr) {
    asm volatile("ldmatrix.sync.aligned.m8n8.x4.shared.b16 {%0,%1,%2,%3}, [%4];"
                 : "=r"(r0), "=r"(r1), "=r"(r2), "=r"(r3) : "r"(addr));
}
__device__ __forceinline__ void mma16816(float* c, const uint32_t* a, const uint32_t* b) {
    asm volatile(
        "mma.sync.aligned.m16n8k16.row.col.f32.f16.f16.f32 "
        "{%0,%1,%2,%3}, {%4,%5,%6,%7}, {%8,%9}, {%0,%1,%2,%3};"
        : "+f"(c[0]), "+f"(c[1]), "+f"(c[2]), "+f"(c[3])
        : "r"(a[0]), "r"(a[1]), "r"(a[2]), "r"(a[3]), "r"(b[0]), "r"(b[1]));
}

// ---------------- fused convert(+scale) + row sum-of-squares -----------------
// One block per row: x rows then W rows. Conversion loop is float4-vectorized;
// the x2/w2 loop is kept BIT-IDENTICAL to R10's rowsq (scalar strided fmaf +
// same shared tree) so winner tie behavior is unchanged. Second read is L1-warm.
__global__ void convsq_kernel(const float* __restrict__ X, const float* __restrict__ W,
                              __half* __restrict__ xh, __half* __restrict__ Wh,
                              float* __restrict__ ox, float* __restrict__ ow)
{
    int row = blockIdx.x;
    const float* p;
    __half* d;
    float scale;
    float* o;
    if (row < BROWS) { p = X + (size_t)row * DIN; d = xh + (size_t)row * DIN; scale = XSCALE; o = ox + row; }
    else { int r = row - BROWS; p = W + (size_t)r * DIN; d = Wh + (size_t)r * DIN; scale = WSCALE; o = ow + r; }

    // convert (vectorized)
    for (int i = threadIdx.x; i < DIN / 4; i += 256) {
        float4 v = ((const float4*)p)[i];
        __half2 a = __halves2half2(__float2half_rn(v.x * scale), __float2half_rn(v.y * scale));
        __half2 b = __halves2half2(__float2half_rn(v.z * scale), __float2half_rn(v.w * scale));
        uint2 u;
        u.x = *(const uint32_t*)&a; u.y = *(const uint32_t*)&b;
        ((uint2*)d)[i] = u;
    }
    // sum of squares (identical structure to R10 rowsq)
    float s = 0.f;
    for (int i = threadIdx.x; i < DIN; i += 256) {
        float v = p[i];
        s = fmaf(v, v, s);
    }
    __shared__ float red[256];
    red[threadIdx.x] = s;
    __syncthreads();
    for (int st = 128; st > 0; st >>= 1) {
        if (threadIdx.x < st) red[threadIdx.x] += red[threadIdx.x + st];
        __syncthreads();
    }
    if (threadIdx.x == 0) *o = red[0];
}

// convert three weight arrays in one launch
__global__ void f2h3_kernel(const float4* __restrict__ s0, uint2* __restrict__ d0, int n0,
                            const float4* __restrict__ s1, uint2* __restrict__ d1, int n1,
                            const float4* __restrict__ s2, uint2* __restrict__ d2, int n2)
{
    int i = blockIdx.x * 256 + threadIdx.x;
    const float4* s; uint2* d;
    if (i < n0) { s = s0 + i; d = d0 + i; }
    else if (i < n0 + n1) { s = s1 + (i - n0); d = d1 + (i - n0); }
    else if (i < n0 + n1 + n2) { s = s2 + (i - n0 - n1); d = d2 + (i - n0 - n1); }
    else return;
    float4 v = *s;
    __half2 a = __halves2half2(__float2half_rn(v.x), __float2half_rn(v.y));
    __half2 b = __halves2half2(__float2half_rn(v.z), __float2half_rn(v.w));
    uint2 o;
    o.x = *(const uint32_t*)&a; o.y = *(const uint32_t*)&b;
    *d = o;
}

// ---------------- stage loader -----------------------------------------------
__device__ __forceinline__ void load_tile(
    const __half* __restrict__ A, const __half* __restrict__ Bm,
    int bm, int bn, int Nb, int K, int kt, int s, uint32_t sbase, int tid)
{
    uint32_t stg = sbase + (uint32_t)s * 2 * TILE_B;
    const uint32_t aT = stg;
    const uint32_t bT = stg + TILE_B;

    const size_t aoff = (size_t)bm * K + (size_t)kt * BK;
#pragma unroll
    for (int i = 0; i < 4; i++) {               // 1024 chunks / 256 threads
        int c = tid + i * 256;
        int r = c >> 3, ch = c & 7;             // 8 x 16B chunks per 128B row
        cpa16(aT + (uint32_t)(r * LDT + ch * 8) * 2,
              A + aoff + (size_t)r * K + ch * 8, 16);
    }
    const size_t boff = (size_t)kt * BK;
#pragma unroll
    for (int i = 0; i < 4; i++) {
        int c = tid + i * 256;
        int r = c >> 3, ch = c & 7;
        int grow = bn + r;
        int ok = (grow < Nb) ? 16 : 0;
        if (grow >= Nb) grow = Nb - 1;
        cpa16(bT + (uint32_t)(r * LDT + ch * 8) * 2,
              Bm + boff + (size_t)grow * K + ch * 8, ok);
    }
}

// ---------------- fp16 mma.sync GEMM: C = A @ B^T + epilogue -----------------
// EPI 0: logits -> float C;  EPI 1: relu+bias -> fp16 C;  EPI 2: bias -> float C
template<int EPI>
__global__ __launch_bounds__(256)
void tc_gemm(const __half* __restrict__ A, const __half* __restrict__ Bm,
             void* __restrict__ Cv, int Nb, int K,
             const float* __restrict__ aux0, const float* __restrict__ aux1)
{
    extern __shared__ char dsm[];
    const int tid  = threadIdx.x;
    const int wid  = tid >> 5;
    const int lane = tid & 31;
    const int wm   = wid & 3;        // 4 warp-rows of 32 m
    const int wn   = wid >> 2;       // 2 warp-cols of 64 n
    const int bm   = blockIdx.x * BM;
    const int bn   = blockIdx.y * BN;
    const uint32_t sbase = smem_u32(dsm);

    float acc[2][8][4];
#pragma unroll
    for (int mt = 0; mt < 2; mt++)
#pragma unroll
        for (int nt = 0; nt < 8; nt++)
#pragma unroll
            for (int i = 0; i < 4; i++) acc[mt][nt][i] = 0.f;

    const int T = K / BK;
    const int lrow = lane & 15;
    const int lcol = (lane >> 4) * 8;

#pragma unroll
    for (int p = 0; p < STG - 1; p++) {
        load_tile(A, Bm, bm, bn, Nb, K, p, p, sbase, tid);
        cpa_commit();
    }

    uint32_t ah[2][2][4];            // [buf][mt][frag]
    uint32_t bh[2][8][2];            // [buf][nt][frag]

    for (int t = 0; t < T; t++) {
        asm volatile("cp.async.wait_group %0;" :: "n"(STG - 2) : "memory");
        __syncthreads();

        int tn = t + STG - 1;        // issue next tile before compute
        if (tn < T)
            load_tile(A, Bm, bm, bn, Nb, K, tn, tn % STG, sbase, tid);
        cpa_commit();

        int s = t % STG;
        uint32_t stg = sbase + (uint32_t)s * 2 * TILE_B;
        const uint32_t aT = stg;
        const uint32_t bT = stg + TILE_B;

        uint32_t aro[2], bro[4];
#pragma unroll
        for (int mt = 0; mt < 2; mt++)
            aro[mt] = (uint32_t)((wm * 32 + mt * 16 + lrow) * LDT) * 2;
#pragma unroll
        for (int np = 0; np < 4; np++)
            bro[np] = (uint32_t)((wn * 64 + np * 16 + lrow) * LDT) * 2;

        auto ldfr = [&](int bu, int ks) {
            uint32_t fo = (uint32_t)(ks * 16 + lcol) * 2;
#pragma unroll
            for (int mt = 0; mt < 2; mt++)
                ldm_x4(ah[bu][mt][0], ah[bu][mt][1], ah[bu][mt][2], ah[bu][mt][3],
                       aT + aro[mt] + fo);
#pragma unroll
            for (int np = 0; np < 4; np++) {
                uint32_t r0, r1, r2, r3;
                ldm_x4(r0, r1, r2, r3, bT + bro[np] + fo);
                bh[bu][2*np][0] = r0; bh[bu][2*np+1][0] = r1;
                bh[bu][2*np][1] = r2; bh[bu][2*np+1][1] = r3;
            }
        };

        ldfr(0, 0);
#pragma unroll
        for (int ks = 0; ks < BK / 16; ks++) {
            int cur = ks & 1;
            if (ks + 1 < BK / 16) ldfr(cur ^ 1, ks + 1);
#pragma unroll
            for (int mt = 0; mt < 2; mt++)
#pragma unroll
                for (int nt = 0; nt < 8; nt++)
                    mma16816(acc[mt][nt], ah[cur][mt], bh[cur][nt]);
        }
    }

    // ---- epilogue ----
    const int r0 = lane >> 2;
    const int c0 = (lane & 3) * 2;
#pragma unroll
    for (int mt = 0; mt < 2; mt++) {
#pragma unroll
        for (int nt = 0; nt < 8; nt++) {
#pragma unroll
            for (int half = 0; half < 2; half++) {
                int m = bm + wm * 32 + mt * 16 + r0 + half * 8;
#pragma unroll
                for (int e = 0; e < 2; e++) {
                    int n = bn + wn * 64 + nt * 8 + c0 + e;
                    if (n >= Nb) continue;
                    float v = acc[mt][nt][half * 2 + e];
                    if (EPI == 0) {
                        float d2 = aux0[m] + aux1[n] - 2.f * (v * INV_SCALE);
                        ((float*)Cv)[(size_t)m * Nb + n] =
                            -TEMP_INV * sqrtf(fmaxf(d2, 1e-12f));
                    } else if (EPI == 1) {
                        ((__half*)Cv)[(size_t)m * Nb + n] =
                            __float2half_rn(fmaxf(v + aux0[n], 0.f));
                    } else {
                        ((float*)Cv)[(size_t)m * Nb + n] = v + aux0[n];
                    }
                }
            }
        }
    }
}

// ---------------- softmax (fp16 out) + winner recheck ------------------------
// Exact fp32 d2 per candidate (256-thread strided + tree), ranked by fp32
// DISTANCE = sqrtf(d2) with lowest-index tie-break. The sqrt collapse (grain
// 3.4e-4 in d2 at d~45) absorbs the ~1e-4 accumulation-order differences
// (validated: R9 chain/tree equivalence; R10 pass).
__global__ __launch_bounds__(256)
void softmax_fix_kernel(const float* __restrict__ S, __half* __restrict__ Sb,
                        float* __restrict__ winners,
                        const float* __restrict__ x, const float* __restrict__ W,
                        const float* __restrict__ x2v, const float* __restrict__ w2v)
{
    const int row = blockIdx.x;
    const int tid = threadIdx.x;
    const float* p = S + (size_t)row * HDIM;

    __shared__ float sv[256];
    __shared__ int   cand[64];
    __shared__ int   nc;
    __shared__ float xs[DIN];

    float v[16];
    float best = -1e30f;
#pragma unroll
    for (int t = 0; t < 16; t++) {
        v[t] = p[tid + t * 256];
        best = fmaxf(best, v[t]);
    }
    sv[tid] = best;
    if (tid == 0) nc = 0;
    __syncthreads();
    for (int st = 128; st > 0; st >>= 1) {
        if (tid < st) sv[tid] = fmaxf(sv[tid], sv[tid + st]);
        __syncthreads();
    }
    const float mx = sv[0];
    __syncthreads();

    // --- candidates within MARGIN of the max logit ---
    const float thr = mx - MARGIN;
#pragma unroll
    for (int t = 0; t < 16; t++)
        if (v[t] >= thr) {
            int s2 = atomicAdd(&nc, 1);
            if (s2 < 64) cand[s2] = tid + t * 256;
        }
    // stage x row (coalesced; reused across candidates)
    for (int k = tid; k < DIN; k += 256) xs[k] = x[(size_t)row * DIN + k];
    __syncthreads();
    const int ncl = nc < 64 ? nc : 64;

    // --- exact recheck: parallel fp32 dot -> DISTANCE (sqrt) ranking ---
    __shared__ float bd;
    __shared__ int   bidx;
    if (tid == 0) { bd = 3.4e38f; bidx = 0x7fffffff; }
    __syncthreads();
    for (int c = 0; c < ncl; c++) {
        int idx = cand[c];
        const float* wr = W + (size_t)idx * DIN;
        float s2 = 0.f;
        for (int k = tid; k < DIN; k += 256) s2 = fmaf(xs[k], wr[k], s2);
        sv[tid] = s2;
        __syncthreads();
        for (int st = 128; st > 0; st >>= 1) {
            if (tid < st) sv[tid] += sv[tid + st];
            __syncthreads();
        }
        if (tid == 0) {
            float d2 = x2v[row] + w2v[idx] - 2.f * sv[0];
            float d = sqrtf(fmaxf(d2, 1e-12f));          // rank by fp32 distance
            if (d < bd || (d == bd && idx < bidx)) { bd = d; bidx = idx; }
        }
        __syncthreads();
    }
    if (tid == 0) winners[row] = (float)bidx;

    // --- softmax -> fp16 ---
    float s = 0.f;
#pragma unroll
    for (int t = 0; t < 16; t++) {
        v[t] = expf(v[t] - mx);
        s += v[t];
    }
    sv[tid] = s;
    __syncthreads();
    for (int st = 128; st > 0; st >>= 1) {
        if (tid < st) sv[tid] += sv[tid + st];
        __syncthreads();
    }
    const float inv = 1.f / sv[0];
    __half* ob = Sb + (size_t)row * HDIM;
#pragma unroll
    for (int t = 0; t < 16; t++)
        ob[tid + t * 256] = __float2half_rn(v[t] * inv);
}

// ---------------- launcher --------------------------------------------------
extern "C" void kernel_launch(void* const* d_in, const int* in_sizes, int n_in,
                              void* d_out, int out_size)
{
    const float* x  = (const float*)d_in[0];
    const float* W  = (const float*)d_in[1];
    const float* w1 = (const float*)d_in[2];
    const float* b1 = (const float*)d_in[3];
    const float* w2 = (const float*)d_in[4];
    const float* b2 = (const float*)d_in[5];
    const float* w3 = (const float*)d_in[6];
    const float* b3 = (const float*)d_in[7];
    float* out = (float*)d_out;

    float *S, *x2, *wsq;
    __half *Sb, *h1, *h2, *xh, *Wh, *w1h, *w2h, *w3h;
    cudaGetSymbolAddress((void**)&S,   g_S);
    cudaGetSymbolAddress((void**)&Sb,  g_Sb);
    cudaGetSymbolAddress((void**)&h1,  g_h1);
    cudaGetSymbolAddress((void**)&h2,  g_h2);
    cudaGetSymbolAddress((void**)&xh,  g_xh);
    cudaGetSymbolAddress((void**)&Wh,  g_Wh);
    cudaGetSymbolAddress((void**)&w1h, g_w1h);
    cudaGetSymbolAddress((void**)&w2h, g_w2h);
    cudaGetSymbolAddress((void**)&w3h, g_w3h);
    cudaGetSymbolAddress((void**)&x2,  g_x2);
    cudaGetSymbolAddress((void**)&wsq, g_w2s);

    cudaFuncSetAttribute(tc_gemm<0>, cudaFuncAttributeMaxDynamicSharedMemorySize, SMEM_STD);
    cudaFuncSetAttribute(tc_gemm<1>, cudaFuncAttributeMaxDynamicSharedMemorySize, SMEM_STD);
    cudaFuncSetAttribute(tc_gemm<2>, cudaFuncAttributeMaxDynamicSharedMemorySize, SMEM_STD);

    float* winners = out + (size_t)out_size - BROWS;

    // fused conversions: x/W (+x2/w2) and w1/w2/w3
    convsq_kernel<<<BROWS + HDIM, 256>>>(x, W, xh, Wh, x2, wsq);
    {
        int n0 = H1DIM * HDIM / 4, n1 = H2DIM * H1DIM / 4, n2 = OUTD * H2DIM / 4;
        f2h3_kernel<<<(n0 + n1 + n2 + 255) / 256, 256>>>(
            (const float4*)w1, (uint2*)w1h, n0,
            (const float4*)w2, (uint2*)w2h, n1,
            (const float4*)w3, (uint2*)w3h, n2);
    }

    // logits = -2*sqrt(x2 + w2 - 2*(xh@Wh^T)/2048)   (single fp16 GEMM)
    tc_gemm<0><<<dim3(BROWS / BM, HDIM / BN), 256, SMEM_STD>>>(
        xh, Wh, S, HDIM, DIN, x2, wsq);

    // softmax + distance-ranked winner recheck
    softmax_fix_kernel<<<BROWS, 256>>>(S, Sb, winners, x, W, x2, wsq);

    // MLP in fp16
    tc_gemm<1><<<dim3(BROWS / BM, H1DIM / BN), 256, SMEM_STD>>>(
        Sb, w1h, h1, H1DIM, HDIM, b1, nullptr);
    tc_gemm<1><<<dim3(BROWS / BM, H2DIM / BN), 256, SMEM_STD>>>(
        h1, w2h, h2, H2DIM, H1DIM, b2, nullptr);
    tc_gemm<2><<<dim3(BROWS / BM, (OUTD + BN - 1) / BN), 256, SMEM_STD>>>(
        h2, w3h, out, OUTD, H2DIM, b3, nullptr);
}

// round 12
// speedup vs baseline: 5.2465x; 1.1404x over previous
#include <cuda_runtime.h>
#include <cuda_fp16.h>
#include <math.h>
#include <stdint.h>

// Problem dims (fixed by dataset)
#define BROWS 4096
#define HDIM  4096
#define DIN   2048
#define H1DIM 2048
#define H2DIM 1024
#define OUTD  1000
#define TEMP_INV 2.0f       // 1/TEMPERATURE
#define XSCALE 32.0f
#define WSCALE 64.0f
#define INV_SCALE (1.0f / 2048.0f)   // 1/(XSCALE*WSCALE), exact power of 2
#define MARGIN 0.005f       // logit margin for winner recheck (~140 sigma of fp16 noise)

// GEMM tiling (fp16 mma.sync m16n8k16)
#define BM 128
#define BN 128
#define BK 64
#define PAD 8
#define LDT (BK + PAD)                       // 72 halves per smem row (144 B)
#define TILE_B (128 * LDT * 2)               // one 128-row tile: 18432 B
#define STG 3
#define SMEM_STD (STG * 2 * TILE_B)          // 110592 B -> 2 CTAs/SM

// ---------------- scratch (static device globals; no allocs allowed) --------
__device__ float  g_S  [(size_t)BROWS * HDIM];   // fp32 logits
__device__ __half g_Sb [(size_t)BROWS * HDIM];   // fp16 softmax
__device__ __half g_h1 [(size_t)BROWS * H1DIM];
__device__ __half g_h2 [(size_t)BROWS * H2DIM];
__device__ __half g_xh [(size_t)BROWS * DIN];
__device__ __half g_Wh [(size_t)HDIM * DIN];
__device__ __half g_w1h[(size_t)H1DIM * HDIM];
__device__ __half g_w2h[(size_t)H2DIM * H1DIM];
__device__ __half g_w3h[(size_t)OUTD * H2DIM];
__device__ float  g_x2[BROWS];
__device__ float  g_w2s[HDIM];

// ---------------- PTX helpers ------------------------------------------------
__device__ __forceinline__ uint32_t smem_u32(const void* p) {
    uint32_t a;
    asm("{ .reg .u64 t; cvta.to.shared.u64 t, %1; cvt.u32.u64 %0, t; }"
        : "=r"(a) : "l"(p));
    return a;
}
__device__ __forceinline__ void cpa16(uint32_t s, const void* g, int sz) {
    asm volatile("cp.async.cg.shared.global [%0], [%1], 16, %2;"
                 :: "r"(s), "l"(g), "r"(sz));
}
__device__ __forceinline__ void cpa_commit() {
    asm volatile("cp.async.commit_group;" ::: "memory");
}
__device__ __forceinline__ void ldm_x4(uint32_t& r0, uint32_t& r1,
                                       uint32_t& r2, uint32_t& r3, uint32_t addr) {
    asm volatile("ldmatrix.sync.aligned.m8n8.x4.shared.b16 {%0,%1,%2,%3}, [%4];"
                 : "=r"(r0), "=r"(r1), "=r"(r2), "=r"(r3) : "r"(addr));
}
__device__ __forceinline__ void mma16816(float* c, const uint32_t* a, const uint32_t* b) {
    asm volatile(
        "mma.sync.aligned.m16n8k16.row.col.f32.f16.f16.f32 "
        "{%0,%1,%2,%3}, {%4,%5,%6,%7}, {%8,%9}, {%0,%1,%2,%3};"
        : "+f"(c[0]), "+f"(c[1]), "+f"(c[2]), "+f"(c[3])
        : "r"(a[0]), "r"(a[1]), "r"(a[2]), "r"(a[3]), "r"(b[0]), "r"(b[1]));
}

// ---------------- fused convert(+scale) + row sum-of-squares -----------------
// One block per row: x rows then W rows. x2/w2 loop kept BIT-IDENTICAL to the
// R10/R11 rowsq (scalar strided fmaf + shared tree) so tie behavior is frozen.
__global__ void convsq_kernel(const float* __restrict__ X, const float* __restrict__ W,
                              __half* __restrict__ xh, __half* __restrict__ Wh,
                              float* __restrict__ ox, float* __restrict__ ow)
{
    int row = blockIdx.x;
    const float* p;
    __half* d;
    float scale;
    float* o;
    if (row < BROWS) { p = X + (size_t)row * DIN; d = xh + (size_t)row * DIN; scale = XSCALE; o = ox + row; }
    else { int r = row - BROWS; p = W + (size_t)r * DIN; d = Wh + (size_t)r * DIN; scale = WSCALE; o = ow + r; }

    for (int i = threadIdx.x; i < DIN / 4; i += 256) {
        float4 v = ((const float4*)p)[i];
        __half2 a = __halves2half2(__float2half_rn(v.x * scale), __float2half_rn(v.y * scale));
        __half2 b = __halves2half2(__float2half_rn(v.z * scale), __float2half_rn(v.w * scale));
        uint2 u;
        u.x = *(const uint32_t*)&a; u.y = *(const uint32_t*)&b;
        ((uint2*)d)[i] = u;
    }
    float s = 0.f;
    for (int i = threadIdx.x; i < DIN; i += 256) {
        float v = p[i];
        s = fmaf(v, v, s);
    }
    __shared__ float red[256];
    red[threadIdx.x] = s;
    __syncthreads();
    for (int st = 128; st > 0; st >>= 1) {
        if (threadIdx.x < st) red[threadIdx.x] += red[threadIdx.x + st];
        __syncthreads();
    }
    if (threadIdx.x == 0) *o = red[0];
}

// convert three weight arrays in one launch
__global__ void f2h3_kernel(const float4* __restrict__ s0, uint2* __restrict__ d0, int n0,
                            const float4* __restrict__ s1, uint2* __restrict__ d1, int n1,
                            const float4* __restrict__ s2, uint2* __restrict__ d2, int n2)
{
    int i = blockIdx.x * 256 + threadIdx.x;
    const float4* s; uint2* d;
    if (i < n0) { s = s0 + i; d = d0 + i; }
    else if (i < n0 + n1) { s = s1 + (i - n0); d = d1 + (i - n0); }
    else if (i < n0 + n1 + n2) { s = s2 + (i - n0 - n1); d = d2 + (i - n0 - n1); }
    else return;
    float4 v = *s;
    __half2 a = __halves2half2(__float2half_rn(v.x), __float2half_rn(v.y));
    __half2 b = __halves2half2(__float2half_rn(v.z), __float2half_rn(v.w));
    uint2 o;
    o.x = *(const uint32_t*)&a; o.y = *(const uint32_t*)&b;
    *d = o;
}

// ---------------- stage loader -----------------------------------------------
__device__ __forceinline__ void load_tile(
    const __half* __restrict__ A, const __half* __restrict__ Bm,
    int bm, int bn, int Nb, int K, int kt, int s, uint32_t sbase, int tid)
{
    uint32_t stg = sbase + (uint32_t)s * 2 * TILE_B;
    const uint32_t aT = stg;
    const uint32_t bT = stg + TILE_B;

    const size_t aoff = (size_t)bm * K + (size_t)kt * BK;
#pragma unroll
    for (int i = 0; i < 4; i++) {               // 1024 chunks / 256 threads
        int c = tid + i * 256;
        int r = c >> 3, ch = c & 7;             // 8 x 16B chunks per 128B row
        cpa16(aT + (uint32_t)(r * LDT + ch * 8) * 2,
              A + aoff + (size_t)r * K + ch * 8, 16);
    }
    const size_t boff = (size_t)kt * BK;
#pragma unroll
    for (int i = 0; i < 4; i++) {
        int c = tid + i * 256;
        int r = c >> 3, ch = c & 7;
        int grow = bn + r;
        int ok = (grow < Nb) ? 16 : 0;
        if (grow >= Nb) grow = Nb - 1;
        cpa16(bT + (uint32_t)(r * LDT + ch * 8) * 2,
              Bm + boff + (size_t)grow * K + ch * 8, ok);
    }
}

// ---------------- fp16 mma.sync GEMM: C = A @ B^T + epilogue -----------------
// EPI 0: logits -> float C;  EPI 1: relu+bias -> fp16 C;  EPI 2: bias -> float C
template<int EPI>
__global__ __launch_bounds__(256)
void tc_gemm(const __half* __restrict__ A, const __half* __restrict__ Bm,
             void* __restrict__ Cv, int Nb, int K,
             const float* __restrict__ aux0, const float* __restrict__ aux1)
{
    extern __shared__ char dsm[];
    const int tid  = threadIdx.x;
    const int wid  = tid >> 5;
    const int lane = tid & 31;
    const int wm   = wid & 3;        // 4 warp-rows of 32 m
    const int wn   = wid >> 2;       // 2 warp-cols of 64 n
    const int bm   = blockIdx.x * BM;
    const int bn   = blockIdx.y * BN;
    const uint32_t sbase = smem_u32(dsm);

    float acc[2][8][4];
#pragma unroll
    for (int mt = 0; mt < 2; mt++)
#pragma unroll
        for (int nt = 0; nt < 8; nt++)
#pragma unroll
            for (int i = 0; i < 4; i++) acc[mt][nt][i] = 0.f;

    const int T = K / BK;
    const int lrow = lane & 15;
    const int lcol = (lane >> 4) * 8;

#pragma unroll
    for (int p = 0; p < STG - 1; p++) {
        load_tile(A, Bm, bm, bn, Nb, K, p, p, sbase, tid);
        cpa_commit();
    }

    uint32_t ah[2][2][4];            // [buf][mt][frag]
    uint32_t bh[2][8][2];            // [buf][nt][frag]

    for (int t = 0; t < T; t++) {
        asm volatile("cp.async.wait_group %0;" :: "n"(STG - 2) : "memory");
        __syncthreads();

        int tn = t + STG - 1;        // issue next tile before compute
        if (tn < T)
            load_tile(A, Bm, bm, bn, Nb, K, tn, tn % STG, sbase, tid);
        cpa_commit();

        int s = t % STG;
        uint32_t stg = sbase + (uint32_t)s * 2 * TILE_B;
        const uint32_t aT = stg;
        const uint32_t bT = stg + TILE_B;

        uint32_t aro[2], bro[4];
#pragma unroll
        for (int mt = 0; mt < 2; mt++)
            aro[mt] = (uint32_t)((wm * 32 + mt * 16 + lrow) * LDT) * 2;
#pragma unroll
        for (int np = 0; np < 4; np++)
            bro[np] = (uint32_t)((wn * 64 + np * 16 + lrow) * LDT) * 2;

        auto ldfr = [&](int bu, int ks) {
            uint32_t fo = (uint32_t)(ks * 16 + lcol) * 2;
#pragma unroll
            for (int mt = 0; mt < 2; mt++)
                ldm_x4(ah[bu][mt][0], ah[bu][mt][1], ah[bu][mt][2], ah[bu][mt][3],
                       aT + aro[mt] + fo);
#pragma unroll
            for (int np = 0; np < 4; np++) {
                uint32_t r0, r1, r2, r3;
                ldm_x4(r0, r1, r2, r3, bT + bro[np] + fo);
                bh[bu][2*np][0] = r0; bh[bu][2*np+1][0] = r1;
                bh[bu][2*np][1] = r2; bh[bu][2*np+1][1] = r3;
            }
        };

        ldfr(0, 0);
#pragma unroll
        for (int ks = 0; ks < BK / 16; ks++) {
            int cur = ks & 1;
            if (ks + 1 < BK / 16) ldfr(cur ^ 1, ks + 1);
#pragma unroll
            for (int mt = 0; mt < 2; mt++)
#pragma unroll
                for (int nt = 0; nt < 8; nt++)
                    mma16816(acc[mt][nt], ah[cur][mt], bh[cur][nt]);
        }
    }

    // ---- epilogue ----
    const int r0 = lane >> 2;
    const int c0 = (lane & 3) * 2;
#pragma unroll
    for (int mt = 0; mt < 2; mt++) {
#pragma unroll
        for (int nt = 0; nt < 8; nt++) {
#pragma unroll
            for (int half = 0; half < 2; half++) {
                int m = bm + wm * 32 + mt * 16 + r0 + half * 8;
#pragma unroll
                for (int e = 0; e < 2; e++) {
                    int n = bn + wn * 64 + nt * 8 + c0 + e;
                    if (n >= Nb) continue;
                    float v = acc[mt][nt][half * 2 + e];
                    if (EPI == 0) {
                        float d2 = aux0[m] + aux1[n] - 2.f * (v * INV_SCALE);
                        ((float*)Cv)[(size_t)m * Nb + n] =
                            -TEMP_INV * sqrtf(fmaxf(d2, 1e-12f));
                    } else if (EPI == 1) {
                        ((__half*)Cv)[(size_t)m * Nb + n] =
                            __float2half_rn(fmaxf(v + aux0[n], 0.f));
                    } else {
                        ((float*)Cv)[(size_t)m * Nb + n] = v + aux0[n];
                    }
                }
            }
        }
    }
}

// ---------------- softmax (fp16 out) + winner recheck ------------------------
// Exact fp32 d2 per candidate (one WARP per candidate: lane-strided dot +
// shfl butterfly — no block syncs), ranked by fp32 DISTANCE = sqrtf(d2) with
// lowest-index tie-break. The sqrt collapse (grain 3.4e-4 in d2 at d~45)
// absorbs accumulation-order differences ~1e-4 (validated R10/R11).
__global__ __launch_bounds__(256)
void softmax_fix_kernel(const float* __restrict__ S, __half* __restrict__ Sb,
                        float* __restrict__ winners,
                        const float* __restrict__ x, const float* __restrict__ W,
                        const float* __restrict__ x2v, const float* __restrict__ w2v)
{
    const int row = blockIdx.x;
    const int tid = threadIdx.x;
    const int wid = tid >> 5;
    const int lane = tid & 31;
    const float* p = S + (size_t)row * HDIM;

    __shared__ float sv[256];
    __shared__ int   cand[64];
    __shared__ int   nc;
    __shared__ float cds[64];
    __shared__ float xs[DIN];

    float v[16];
    float best = -1e30f;
#pragma unroll
    for (int t = 0; t < 16; t++) {
        v[t] = p[tid + t * 256];
        best = fmaxf(best, v[t]);
    }
    sv[tid] = best;
    if (tid == 0) nc = 0;
    __syncthreads();
    for (int st = 128; st > 0; st >>= 1) {
        if (tid < st) sv[tid] = fmaxf(sv[tid], sv[tid + st]);
        __syncthreads();
    }
    const float mx = sv[0];
    __syncthreads();

    // --- candidates within MARGIN of the max logit ---
    const float thr = mx - MARGIN;
#pragma unroll
    for (int t = 0; t < 16; t++)
        if (v[t] >= thr) {
            int s2 = atomicAdd(&nc, 1);
            if (s2 < 64) cand[s2] = tid + t * 256;
        }
    // stage x row (coalesced; reused across candidates)
    for (int k = tid; k < DIN; k += 256) xs[k] = x[(size_t)row * DIN + k];
    __syncthreads();
    const int ncl = nc < 64 ? nc : 64;

    // --- exact recheck: one warp per candidate, shfl reduce ---
    for (int c = wid; c < ncl; c += 8) {
        int idx = cand[c];
        const float* wr = W + (size_t)idx * DIN;
        float s2 = 0.f;
        for (int k = lane; k < DIN; k += 32) s2 = fmaf(xs[k], wr[k], s2);
#pragma unroll
        for (int off = 16; off > 0; off >>= 1)
            s2 += __shfl_xor_sync(0xffffffff, s2, off);
        if (lane == 0) {
            float d2 = x2v[row] + w2v[idx] - 2.f * s2;
            cds[c] = sqrtf(fmaxf(d2, 1e-12f));   // rank by fp32 distance
        }
    }
    __syncthreads();
    if (tid == 0) {
        float bd = 3.4e38f;
        int bidx = 0x7fffffff;
        for (int c = 0; c < ncl; c++) {
            float d = cds[c];
            int idx = cand[c];
            if (d < bd || (d == bd && idx < bidx)) { bd = d; bidx = idx; }
        }
        winners[row] = (float)bidx;
    }

    // --- softmax -> fp16 ---
    float s = 0.f;
#pragma unroll
    for (int t = 0; t < 16; t++) {
        v[t] = expf(v[t] - mx);
        s += v[t];
    }
    sv[tid] = s;
    __syncthreads();
    for (int st = 128; st > 0; st >>= 1) {
        if (tid < st) sv[tid] += sv[tid + st];
        __syncthreads();
    }
    const float inv = 1.f / sv[0];
    __half* ob = Sb + (size_t)row * HDIM;
#pragma unroll
    for (int t = 0; t < 16; t++)
        ob[tid + t * 256] = __float2half_rn(v[t] * inv);
}

// ---------------- launcher --------------------------------------------------
extern "C" void kernel_launch(void* const* d_in, const int* in_sizes, int n_in,
                              void* d_out, int out_size)
{
    const float* x  = (const float*)d_in[0];
    const float* W  = (const float*)d_in[1];
    const float* w1 = (const float*)d_in[2];
    const float* b1 = (const float*)d_in[3];
    const float* w2 = (const float*)d_in[4];
    const float* b2 = (const float*)d_in[5];
    const float* w3 = (const float*)d_in[6];
    const float* b3 = (const float*)d_in[7];
    float* out = (float*)d_out;

    float *S, *x2, *wsq;
    __half *Sb, *h1, *h2, *xh, *Wh, *w1h, *w2h, *w3h;
    cudaGetSymbolAddress((void**)&S,   g_S);
    cudaGetSymbolAddress((void**)&Sb,  g_Sb);
    cudaGetSymbolAddress((void**)&h1,  g_h1);
    cudaGetSymbolAddress((void**)&h2,  g_h2);
    cudaGetSymbolAddress((void**)&xh,  g_xh);
    cudaGetSymbolAddress((void**)&Wh,  g_Wh);
    cudaGetSymbolAddress((void**)&w1h, g_w1h);
    cudaGetSymbolAddress((void**)&w2h, g_w2h);
    cudaGetSymbolAddress((void**)&w3h, g_w3h);
    cudaGetSymbolAddress((void**)&x2,  g_x2);
    cudaGetSymbolAddress((void**)&wsq, g_w2s);

    cudaFuncSetAttribute(tc_gemm<0>, cudaFuncAttributeMaxDynamicSharedMemorySize, SMEM_STD);
    cudaFuncSetAttribute(tc_gemm<1>, cudaFuncAttributeMaxDynamicSharedMemorySize, SMEM_STD);
    cudaFuncSetAttribute(tc_gemm<2>, cudaFuncAttributeMaxDynamicSharedMemorySize, SMEM_STD);

    float* winners = out + (size_t)out_size - BROWS;

    // fused conversions: x/W (+x2/w2) and w1/w2/w3
    convsq_kernel<<<BROWS + HDIM, 256>>>(x, W, xh, Wh, x2, wsq);
    {
        int n0 = H1DIM * HDIM / 4, n1 = H2DIM * H1DIM / 4, n2 = OUTD * H2DIM / 4;
        f2h3_kernel<<<(n0 + n1 + n2 + 255) / 256, 256>>>(
            (const float4*)w1, (uint2*)w1h, n0,
            (const float4*)w2, (uint2*)w2h, n1,
            (const float4*)w3, (uint2*)w3h, n2);
    }

    // logits = -2*sqrt(x2 + w2 - 2*(xh@Wh^T)/2048)   (single fp16 GEMM)
    tc_gemm<0><<<dim3(BROWS / BM, HDIM / BN), 256, SMEM_STD>>>(
        xh, Wh, S, HDIM, DIN, x2, wsq);

    // softmax + distance-ranked winner recheck
    softmax_fix_kernel<<<BROWS, 256>>>(S, Sb, winners, x, W, x2, wsq);

    // MLP in fp16
    tc_gemm<1><<<dim3(BROWS / BM, H1DIM / BN), 256, SMEM_STD>>>(
        Sb, w1h, h1, H1DIM, HDIM, b1, nullptr);
    tc_gemm<1><<<dim3(BROWS / BM, H2DIM / BN), 256, SMEM_STD>>>(
        h1, w2h, h2, H2DIM, H1DIM, b2, nullptr);
    tc_gemm<2><<<dim3(BROWS / BM, (OUTD + BN - 1) / BN), 256, SMEM_STD>>>(
        h2, w3h, out, OUTD, H2DIM, b3, nullptr);
}

// round 13
// speedup vs baseline: 5.3755x; 1.0246x over previous
#include <cuda_runtime.h>
#include <cuda_fp16.h>
#include <math.h>
#include <stdint.h>

// Problem dims (fixed by dataset)
#define BROWS 4096
#define HDIM  4096
#define DIN   2048
#define H1DIM 2048
#define H2DIM 1024
#define OUTD  1000
#define TEMP_INV 2.0f       // 1/TEMPERATURE
#define XSCALE 32.0f
#define WSCALE 64.0f
#define INV_SCALE (1.0f / 2048.0f)   // 1/(XSCALE*WSCALE), exact power of 2
#define MARGIN 0.005f       // logit margin for winner recheck (~140 sigma of fp16 noise)
#define MAXC 16             // candidate cap per row

// GEMM tiling (fp16 mma.sync m16n8k16)
#define BM 128
#define BN 128
#define BK 64
#define PAD 8
#define LDT (BK + PAD)                       // 72 halves per smem row (144 B)
#define TILE_B (128 * LDT * 2)               // one 128-row tile: 18432 B
#define STG 3
#define SMEM_STD (STG * 2 * TILE_B)          // 110592 B -> 2 CTAs/SM

// ---------------- scratch (static device globals; no allocs allowed) --------
__device__ float  g_S  [(size_t)BROWS * HDIM];   // fp32 logits
__device__ __half g_Sb [(size_t)BROWS * HDIM];   // fp16 softmax
__device__ __half g_h1 [(size_t)BROWS * H1DIM];
__device__ __half g_h2 [(size_t)BROWS * H2DIM];
__device__ __half g_xh [(size_t)BROWS * DIN];
__device__ __half g_Wh [(size_t)HDIM * DIN];
__device__ __half g_w1h[(size_t)H1DIM * HDIM];
__device__ __half g_w2h[(size_t)H2DIM * H1DIM];
__device__ __half g_w3h[(size_t)OUTD * H2DIM];
__device__ float  g_x2[BROWS];
__device__ float  g_w2s[HDIM];
__device__ int    g_cand[(size_t)BROWS * MAXC];
__device__ int    g_nc[BROWS];

// ---------------- PTX helpers ------------------------------------------------
__device__ __forceinline__ uint32_t smem_u32(const void* p) {
    uint32_t a;
    asm("{ .reg .u64 t; cvta.to.shared.u64 t, %1; cvt.u32.u64 %0, t; }"
        : "=r"(a) : "l"(p));
    return a;
}
__device__ __forceinline__ void cpa16(uint32_t s, const void* g, int sz) {
    asm volatile("cp.async.cg.shared.global [%0], [%1], 16, %2;"
                 :: "r"(s), "l"(g), "r"(sz));
}
__device__ __forceinline__ void cpa_commit() {
    asm volatile("cp.async.commit_group;" ::: "memory");
}
__device__ __forceinline__ void ldm_x4(uint32_t& r0, uint32_t& r1,
                                       uint32_t& r2, uint32_t& r3, uint32_t addr) {
    asm volatile("ldmatrix.sync.aligned.m8n8.x4.shared.b16 {%0,%1,%2,%3}, [%4];"
                 : "=r"(r0), "=r"(r1), "=r"(r2), "=r"(r3) : "r"(addr));
}
__device__ __forceinline__ void mma16816(float* c, const uint32_t* a, const uint32_t* b) {
    asm volatile(
        "mma.sync.aligned.m16n8k16.row.col.f32.f16.f16.f32 "
        "{%0,%1,%2,%3}, {%4,%5,%6,%7}, {%8,%9}, {%0,%1,%2,%3};"
        : "+f"(c[0]), "+f"(c[1]), "+f"(c[2]), "+f"(c[3])
        : "r"(a[0]), "r"(a[1]), "r"(a[2]), "r"(a[3]), "r"(b[0]), "r"(b[1]));
}

// ---------------- fused convert(+scale) + row sum-of-squares -----------------
__global__ void convsq_kernel(const float* __restrict__ X, const float* __restrict__ W,
                              __half* __restrict__ xh, __half* __restrict__ Wh,
                              float* __restrict__ ox, float* __restrict__ ow)
{
    int row = blockIdx.x;
    const float* p;
    __half* d;
    float scale;
    float* o;
    if (row < BROWS) { p = X + (size_t)row * DIN; d = xh + (size_t)row * DIN; scale = XSCALE; o = ox + row; }
    else { int r = row - BROWS; p = W + (size_t)r * DIN; d = Wh + (size_t)r * DIN; scale = WSCALE; o = ow + r; }

    for (int i = threadIdx.x; i < DIN / 4; i += 256) {
        float4 v = ((const float4*)p)[i];
        __half2 a = __halves2half2(__float2half_rn(v.x * scale), __float2half_rn(v.y * scale));
        __half2 b = __halves2half2(__float2half_rn(v.z * scale), __float2half_rn(v.w * scale));
        uint2 u;
        u.x = *(const uint32_t*)&a; u.y = *(const uint32_t*)&b;
        ((uint2*)d)[i] = u;
    }
    float s = 0.f;
    for (int i = threadIdx.x; i < DIN; i += 256) {
        float v = p[i];
        s = fmaf(v, v, s);
    }
    __shared__ float red[256];
    red[threadIdx.x] = s;
    __syncthreads();
    for (int st = 128; st > 0; st >>= 1) {
        if (threadIdx.x < st) red[threadIdx.x] += red[threadIdx.x + st];
        __syncthreads();
    }
    if (threadIdx.x == 0) *o = red[0];
}

// convert three weight arrays in one launch
__global__ void f2h3_kernel(const float4* __restrict__ s0, uint2* __restrict__ d0, int n0,
                            const float4* __restrict__ s1, uint2* __restrict__ d1, int n1,
                            const float4* __restrict__ s2, uint2* __restrict__ d2, int n2)
{
    int i = blockIdx.x * 256 + threadIdx.x;
    const float4* s; uint2* d;
    if (i < n0) { s = s0 + i; d = d0 + i; }
    else if (i < n0 + n1) { s = s1 + (i - n0); d = d1 + (i - n0); }
    else if (i < n0 + n1 + n2) { s = s2 + (i - n0 - n1); d = d2 + (i - n0 - n1); }
    else return;
    float4 v = *s;
    __half2 a = __halves2half2(__float2half_rn(v.x), __float2half_rn(v.y));
    __half2 b = __halves2half2(__float2half_rn(v.z), __float2half_rn(v.w));
    uint2 o;
    o.x = *(const uint32_t*)&a; o.y = *(const uint32_t*)&b;
    *d = o;
}

// ---------------- stage loader -----------------------------------------------
__device__ __forceinline__ void load_tile(
    const __half* __restrict__ A, const __half* __restrict__ Bm,
    int bm, int bn, int Nb, int K, int kt, int s, uint32_t sbase, int tid)
{
    uint32_t stg = sbase + (uint32_t)s * 2 * TILE_B;
    const uint32_t aT = stg;
    const uint32_t bT = stg + TILE_B;

    const size_t aoff = (size_t)bm * K + (size_t)kt * BK;
#pragma unroll
    for (int i = 0; i < 4; i++) {
        int c = tid + i * 256;
        int r = c >> 3, ch = c & 7;
        cpa16(aT + (uint32_t)(r * LDT + ch * 8) * 2,
              A + aoff + (size_t)r * K + ch * 8, 16);
    }
    const size_t boff = (size_t)kt * BK;
#pragma unroll
    for (int i = 0; i < 4; i++) {
        int c = tid + i * 256;
        int r = c >> 3, ch = c & 7;
        int grow = bn + r;
        int ok = (grow < Nb) ? 16 : 0;
        if (grow >= Nb) grow = Nb - 1;
        cpa16(bT + (uint32_t)(r * LDT + ch * 8) * 2,
              Bm + boff + (size_t)grow * K + ch * 8, ok);
    }
}

// ---------------- fp16 mma.sync GEMM: C = A @ B^T + epilogue -----------------
// EPI 0: logits -> float C;  EPI 1: relu+bias -> fp16 C;  EPI 2: bias -> float C
template<int EPI>
__global__ __launch_bounds__(256)
void tc_gemm(const __half* __restrict__ A, const __half* __restrict__ Bm,
             void* __restrict__ Cv, int Nb, int K,
             const float* __restrict__ aux0, const float* __restrict__ aux1)
{
    extern __shared__ char dsm[];
    const int tid  = threadIdx.x;
    const int wid  = tid >> 5;
    const int lane = tid & 31;
    const int wm   = wid & 3;
    const int wn   = wid >> 2;
    const int bm   = blockIdx.x * BM;
    const int bn   = blockIdx.y * BN;
    const uint32_t sbase = smem_u32(dsm);

    float acc[2][8][4];
#pragma unroll
    for (int mt = 0; mt < 2; mt++)
#pragma unroll
        for (int nt = 0; nt < 8; nt++)
#pragma unroll
            for (int i = 0; i < 4; i++) acc[mt][nt][i] = 0.f;

    const int T = K / BK;
    const int lrow = lane & 15;
    const int lcol = (lane >> 4) * 8;

#pragma unroll
    for (int p = 0; p < STG - 1; p++) {
        load_tile(A, Bm, bm, bn, Nb, K, p, p, sbase, tid);
        cpa_commit();
    }

    uint32_t ah[2][2][4];
    uint32_t bh[2][8][2];

    for (int t = 0; t < T; t++) {
        asm volatile("cp.async.wait_group %0;" :: "n"(STG - 2) : "memory");
        __syncthreads();

        int tn = t + STG - 1;
        if (tn < T)
            load_tile(A, Bm, bm, bn, Nb, K, tn, tn % STG, sbase, tid);
        cpa_commit();

        int s = t % STG;
        uint32_t stg = sbase + (uint32_t)s * 2 * TILE_B;
        const uint32_t aT = stg;
        const uint32_t bT = stg + TILE_B;

        uint32_t aro[2], bro[4];
#pragma unroll
        for (int mt = 0; mt < 2; mt++)
            aro[mt] = (uint32_t)((wm * 32 + mt * 16 + lrow) * LDT) * 2;
#pragma unroll
        for (int np = 0; np < 4; np++)
            bro[np] = (uint32_t)((wn * 64 + np * 16 + lrow) * LDT) * 2;

        auto ldfr = [&](int bu, int ks) {
            uint32_t fo = (uint32_t)(ks * 16 + lcol) * 2;
#pragma unroll
            for (int mt = 0; mt < 2; mt++)
                ldm_x4(ah[bu][mt][0], ah[bu][mt][1], ah[bu][mt][2], ah[bu][mt][3],
                       aT + aro[mt] + fo);
#pragma unroll
            for (int np = 0; np < 4; np++) {
                uint32_t r0, r1, r2, r3;
                ldm_x4(r0, r1, r2, r3, bT + bro[np] + fo);
                bh[bu][2*np][0] = r0; bh[bu][2*np+1][0] = r1;
                bh[bu][2*np][1] = r2; bh[bu][2*np+1][1] = r3;
            }
        };

        ldfr(0, 0);
#pragma unroll
        for (int ks = 0; ks < BK / 16; ks++) {
            int cur = ks & 1;
            if (ks + 1 < BK / 16) ldfr(cur ^ 1, ks + 1);
#pragma unroll
            for (int mt = 0; mt < 2; mt++)
#pragma unroll
                for (int nt = 0; nt < 8; nt++)
                    mma16816(acc[mt][nt], ah[cur][mt], bh[cur][nt]);
        }
    }

    // ---- epilogue ----
    const int r0 = lane >> 2;
    const int c0 = (lane & 3) * 2;
#pragma unroll
    for (int mt = 0; mt < 2; mt++) {
#pragma unroll
        for (int nt = 0; nt < 8; nt++) {
#pragma unroll
            for (int half = 0; half < 2; half++) {
                int m = bm + wm * 32 + mt * 16 + r0 + half * 8;
#pragma unroll
                for (int e = 0; e < 2; e++) {
                    int n = bn + wn * 64 + nt * 8 + c0 + e;
                    if (n >= Nb) continue;
                    float v = acc[mt][nt][half * 2 + e];
                    if (EPI == 0) {
                        float d2 = aux0[m] + aux1[n] - 2.f * (v * INV_SCALE);
                        ((float*)Cv)[(size_t)m * Nb + n] =
                            -TEMP_INV * sqrtf(fmaxf(d2, 1e-12f));
                    } else if (EPI == 1) {
                        ((__half*)Cv)[(size_t)m * Nb + n] =
                            __float2half_rn(fmaxf(v + aux0[n], 0.f));
                    } else {
                        ((float*)Cv)[(size_t)m * Nb + n] = v + aux0[n];
                    }
                }
            }
        }
    }
}

// ---------------- softmax (fp16 out) + candidate emission --------------------
// Lean: max, candidates -> global list, __expf softmax -> Sb. No W access.
__global__ __launch_bounds__(256)
void softmax_kernel(const float* __restrict__ S, __half* __restrict__ Sb,
                    int* __restrict__ candbuf, int* __restrict__ ncand)
{
    const int row = blockIdx.x;
    const int tid = threadIdx.x;
    const float4* p4 = (const float4*)(S + (size_t)row * HDIM);

    __shared__ float sv[256];
    __shared__ int snc;

    float4 v4[4];
    float best = -1e30f;
#pragma unroll
    for (int t = 0; t < 4; t++) {
        v4[t] = p4[tid + t * 256];
        best = fmaxf(best, fmaxf(fmaxf(v4[t].x, v4[t].y), fmaxf(v4[t].z, v4[t].w)));
    }
    sv[tid] = best;
    if (tid == 0) snc = 0;
    __syncthreads();
    for (int st = 128; st > 0; st >>= 1) {
        if (tid < st) sv[tid] = fmaxf(sv[tid], sv[tid + st]);
        __syncthreads();
    }
    const float mx = sv[0];
    __syncthreads();

    const float thr = mx - MARGIN;
#pragma unroll
    for (int t = 0; t < 4; t++) {
        int base = (tid + t * 256) * 4;
        float vv[4] = {v4[t].x, v4[t].y, v4[t].z, v4[t].w};
#pragma unroll
        for (int j = 0; j < 4; j++)
            if (vv[j] >= thr) {
                int slot = atomicAdd(&snc, 1);
                if (slot < MAXC) candbuf[(size_t)row * MAXC + slot] = base + j;
            }
    }

    float s = 0.f;
#pragma unroll
    for (int t = 0; t < 4; t++) {
        v4[t].x = __expf(v4[t].x - mx);
        v4[t].y = __expf(v4[t].y - mx);
        v4[t].z = __expf(v4[t].z - mx);
        v4[t].w = __expf(v4[t].w - mx);
        s += (v4[t].x + v4[t].y) + (v4[t].z + v4[t].w);
    }
    sv[tid] = s;
    __syncthreads();
    for (int st = 128; st > 0; st >>= 1) {
        if (tid < st) sv[tid] += sv[tid + st];
        __syncthreads();
    }
    const float inv = 1.f / sv[0];
    if (tid == 0) ncand[row] = snc < MAXC ? snc : MAXC;

    uint2* ob = (uint2*)(Sb + (size_t)row * HDIM);
#pragma unroll
    for (int t = 0; t < 4; t++) {
        __half2 a = __halves2half2(__float2half_rn(v4[t].x * inv), __float2half_rn(v4[t].y * inv));
        __half2 b = __halves2half2(__float2half_rn(v4[t].z * inv), __float2half_rn(v4[t].w * inv));
        uint2 u;
        u.x = *(const uint32_t*)&a; u.y = *(const uint32_t*)&b;
        ob[tid + t * 256] = u;
    }
}

// ---------------- winner recheck (1 warp per row; runs overlapped) -----------
// Exact fp32 dot per candidate (lane-strided + shfl, validated class), ranked
// by fp32 DISTANCE = sqrtf(d2), lowest-index tie-break (R10-validated).
__global__ __launch_bounds__(256)
void recheck_kernel(const int* __restrict__ candbuf, const int* __restrict__ ncand,
                    float* __restrict__ winners,
                    const float* __restrict__ x, const float* __restrict__ W,
                    const float* __restrict__ x2v, const float* __restrict__ w2v)
{
    const int wid = threadIdx.x >> 5;
    const int lane = threadIdx.x & 31;
    const int row = blockIdx.x * 8 + wid;
    if (row >= BROWS) return;

    const float* xr = x + (size_t)row * DIN;
    const int nc = ncand[row];
    float bd = 3.4e38f;
    int bidx = 0x7fffffff;
    for (int c = 0; c < nc; c++) {
        int idx = candbuf[(size_t)row * MAXC + c];
        const float* wr = W + (size_t)idx * DIN;
        float s2 = 0.f;
        for (int k = lane; k < DIN; k += 32) s2 = fmaf(xr[k], wr[k], s2);
#pragma unroll
        for (int off = 16; off > 0; off >>= 1)
            s2 += __shfl_xor_sync(0xffffffff, s2, off);
        float d2 = x2v[row] + w2v[idx] - 2.f * s2;
        float d = sqrtf(fmaxf(d2, 1e-12f));
        if (d < bd || (d == bd && idx < bidx)) { bd = d; bidx = idx; }
    }
    if (lane == 0) winners[row] = (float)bidx;
}

// ---------------- launcher --------------------------------------------------
extern "C" void kernel_launch(void* const* d_in, const int* in_sizes, int n_in,
                              void* d_out, int out_size)
{
    const float* x  = (const float*)d_in[0];
    const float* W  = (const float*)d_in[1];
    const float* w1 = (const float*)d_in[2];
    const float* b1 = (const float*)d_in[3];
    const float* w2 = (const float*)d_in[4];
    const float* b2 = (const float*)d_in[5];
    const float* w3 = (const float*)d_in[6];
    const float* b3 = (const float*)d_in[7];
    float* out = (float*)d_out;

    float *S, *x2, *wsq;
    __half *Sb, *h1, *h2, *xh, *Wh, *w1h, *w2h, *w3h;
    int *cand, *ncv;
    cudaGetSymbolAddress((void**)&S,   g_S);
    cudaGetSymbolAddress((void**)&Sb,  g_Sb);
    cudaGetSymbolAddress((void**)&h1,  g_h1);
    cudaGetSymbolAddress((void**)&h2,  g_h2);
    cudaGetSymbolAddress((void**)&xh,  g_xh);
    cudaGetSymbolAddress((void**)&Wh,  g_Wh);
    cudaGetSymbolAddress((void**)&w1h, g_w1h);
    cudaGetSymbolAddress((void**)&w2h, g_w2h);
    cudaGetSymbolAddress((void**)&w3h, g_w3h);
    cudaGetSymbolAddress((void**)&x2,  g_x2);
    cudaGetSymbolAddress((void**)&wsq, g_w2s);
    cudaGetSymbolAddress((void**)&cand, g_cand);
    cudaGetSymbolAddress((void**)&ncv,  g_nc);

    cudaFuncSetAttribute(tc_gemm<0>, cudaFuncAttributeMaxDynamicSharedMemorySize, SMEM_STD);
    cudaFuncSetAttribute(tc_gemm<1>, cudaFuncAttributeMaxDynamicSharedMemorySize, SMEM_STD);
    cudaFuncSetAttribute(tc_gemm<2>, cudaFuncAttributeMaxDynamicSharedMemorySize, SMEM_STD);

    float* winners = out + (size_t)out_size - BROWS;

    // side stream + events (created once, on the first/non-capture call)
    static cudaStream_t s2 = nullptr;
    static cudaEvent_t evA = nullptr, evB = nullptr, evC = nullptr, evD = nullptr;
    if (!s2) {
        cudaStreamCreateWithFlags(&s2, cudaStreamNonBlocking);
        cudaEventCreateWithFlags(&evA, cudaEventDisableTiming);
        cudaEventCreateWithFlags(&evB, cudaEventDisableTiming);
        cudaEventCreateWithFlags(&evC, cudaEventDisableTiming);
        cudaEventCreateWithFlags(&evD, cudaEventDisableTiming);
    }

    // main: convsq -> gemm0 -> softmax -> [wait w1h] gemm1 -> gemm2 -> gemm3
    // side: f2h3 (under gemm0), recheck (under gemm1+)
    convsq_kernel<<<BROWS + HDIM, 256>>>(x, W, xh, Wh, x2, wsq);
    cudaEventRecord(evA, 0);
    cudaStreamWaitEvent(s2, evA, 0);
    {
        int n0 = H1DIM * HDIM / 4, n1 = H2DIM * H1DIM / 4, n2 = OUTD * H2DIM / 4;
        f2h3_kernel<<<(n0 + n1 + n2 + 255) / 256, 256, 0, s2>>>(
            (const float4*)w1, (uint2*)w1h, n0,
            (const float4*)w2, (uint2*)w2h, n1,
            (const float4*)w3, (uint2*)w3h, n2);
    }
    cudaEventRecord(evB, s2);

    tc_gemm<0><<<dim3(BROWS / BM, HDIM / BN), 256, SMEM_STD>>>(
        xh, Wh, S, HDIM, DIN, x2, wsq);
    softmax_kernel<<<BROWS, 256>>>(S, Sb, cand, ncv);

    cudaEventRecord(evC, 0);
    cudaStreamWaitEvent(s2, evC, 0);
    recheck_kernel<<<BROWS / 8, 256, 0, s2>>>(cand, ncv, winners, x, W, x2, wsq);
    cudaEventRecord(evD, s2);

    cudaStreamWaitEvent(0, evB, 0);   // gemm1 needs w1h/w2h/w3h
    tc_gemm<1><<<dim3(BROWS / BM, H1DIM / BN), 256, SMEM_STD>>>(
        Sb, w1h, h1, H1DIM, HDIM, b1, nullptr);
    tc_gemm<1><<<dim3(BROWS / BM, H2DIM / BN), 256, SMEM_STD>>>(
        h1, w2h, h2, H2DIM, H1DIM, b2, nullptr);
    tc_gemm<2><<<dim3(BROWS / BM, (OUTD + BN - 1) / BN), 256, SMEM_STD>>>(
        h2, w3h, out, OUTD, H2DIM, b3, nullptr);
    cudaStreamWaitEvent(0, evD, 0);   // join: winners complete before graph end
}

// round 16
// speedup vs baseline: 5.7116x; 1.0625x over previous
#include <cuda_runtime.h>
#include <cuda_fp16.h>
#include <math.h>
#include <stdint.h>

// Problem dims (fixed by dataset)
#define BROWS 4096
#define HDIM  4096
#define DIN   2048
#define H1DIM 2048
#define H2DIM 1024
#define OUTD  1000
#define TEMP_INV 2.0f       // 1/TEMPERATURE
#define XSCALE 32.0f
#define WSCALE 64.0f
#define INV_SCALE (1.0f / 2048.0f)   // 1/(XSCALE*WSCALE), exact power of 2
#define MARGIN 0.005f       // logit margin for winner recheck (~140 sigma of fp16 noise)
#define MAXC 16             // candidate cap per row

// GEMM tiling (fp16 mma.sync m16n8k16)
#define BM 128
#define BN 128
#define BK 64
#define PAD 8
#define LDT (BK + PAD)                       // 72 halves per smem row (144 B)
#define TILE_B (128 * LDT * 2)               // one 128-row tile: 18432 B
#define STG 3
#define SMEM_STD (STG * 2 * TILE_B)          // 110592 B -> 2 CTAs/SM

// ---------------- scratch (static device globals; no allocs allowed) --------
__device__ float  g_S  [(size_t)BROWS * HDIM];   // fp32 logits
__device__ __half g_Sb [(size_t)BROWS * HDIM];   // fp16 softmax
__device__ __half g_h1 [(size_t)BROWS * H1DIM];
__device__ __half g_h2 [(size_t)BROWS * H2DIM];
__device__ __half g_xh [(size_t)BROWS * DIN];
__device__ __half g_Wh [(size_t)HDIM * DIN];
__device__ __half g_w1h[(size_t)H1DIM * HDIM];
__device__ __half g_w2h[(size_t)H2DIM * H1DIM];
__device__ __half g_w3h[(size_t)OUTD * H2DIM];
__device__ float  g_x2[BROWS];
__device__ float  g_w2s[HDIM];
__device__ int    g_cand[(size_t)BROWS * MAXC];
__device__ int    g_nc[BROWS];

// ---------------- PTX helpers ------------------------------------------------
__device__ __forceinline__ uint32_t smem_u32(const void* p) {
    uint32_t a;
    asm("{ .reg .u64 t; cvta.to.shared.u64 t, %1; cvt.u32.u64 %0, t; }"
        : "=r"(a) : "l"(p));
    return a;
}
__device__ __forceinline__ void cpa16(uint32_t s, const void* g, int sz) {
    asm volatile("cp.async.cg.shared.global [%0], [%1], 16, %2;"
                 :: "r"(s), "l"(g), "r"(sz));
}
__device__ __forceinline__ void cpa_commit() {
    asm volatile("cp.async.commit_group;" ::: "memory");
}
__device__ __forceinline__ void ldm_x4(uint32_t& r0, uint32_t& r1,
                                       uint32_t& r2, uint32_t& r3, uint32_t addr) {
    asm volatile("ldmatrix.sync.aligned.m8n8.x4.shared.b16 {%0,%1,%2,%3}, [%4];"
                 : "=r"(r0), "=r"(r1), "=r"(r2), "=r"(r3) : "r"(addr));
}
__device__ __forceinline__ void mma16816(float* c, const uint32_t* a, const uint32_t* b) {
    asm volatile(
        "mma.sync.aligned.m16n8k16.row.col.f32.f16.f16.f32 "
        "{%0,%1,%2,%3}, {%4,%5,%6,%7}, {%8,%9}, {%0,%1,%2,%3};"
        : "+f"(c[0]), "+f"(c[1]), "+f"(c[2]), "+f"(c[3])
        : "r"(a[0]), "r"(a[1]), "r"(a[2]), "r"(a[3]), "r"(b[0]), "r"(b[1]));
}

// ---------------- fused convert(+scale) + row sum-of-squares -----------------
__global__ void convsq_kernel(const float* __restrict__ X, const float* __restrict__ W,
                              __half* __restrict__ xh, __half* __restrict__ Wh,
                              float* __restrict__ ox, float* __restrict__ ow)
{
    int row = blockIdx.x;
    const float* p;
    __half* d;
    float scale;
    float* o;
    if (row < BROWS) { p = X + (size_t)row * DIN; d = xh + (size_t)row * DIN; scale = XSCALE; o = ox + row; }
    else { int r = row - BROWS; p = W + (size_t)r * DIN; d = Wh + (size_t)r * DIN; scale = WSCALE; o = ow + r; }

    for (int i = threadIdx.x; i < DIN / 4; i += 256) {
        float4 v = ((const float4*)p)[i];
        __half2 a = __halves2half2(__float2half_rn(v.x * scale), __float2half_rn(v.y * scale));
        __half2 b = __halves2half2(__float2half_rn(v.z * scale), __float2half_rn(v.w * scale));
        uint2 u;
        u.x = *(const uint32_t*)&a; u.y = *(const uint32_t*)&b;
        ((uint2*)d)[i] = u;
    }
    float s = 0.f;
    for (int i = threadIdx.x; i < DIN; i += 256) {
        float v = p[i];
        s = fmaf(v, v, s);
    }
    __shared__ float red[256];
    red[threadIdx.x] = s;
    __syncthreads();
    for (int st = 128; st > 0; st >>= 1) {
        if (threadIdx.x < st) red[threadIdx.x] += red[threadIdx.x + st];
        __syncthreads();
    }
    if (threadIdx.x == 0) *o = red[0];
}

// convert three weight arrays in one launch
__global__ void f2h3_kernel(const float4* __restrict__ s0, uint2* __restrict__ d0, int n0,
                            const float4* __restrict__ s1, uint2* __restrict__ d1, int n1,
                            const float4* __restrict__ s2, uint2* __restrict__ d2, int n2)
{
    int i = blockIdx.x * 256 + threadIdx.x;
    const float4* s; uint2* d;
    if (i < n0) { s = s0 + i; d = d0 + i; }
    else if (i < n0 + n1) { s = s1 + (i - n0); d = d1 + (i - n0); }
    else if (i < n0 + n1 + n2) { s = s2 + (i - n0 - n1); d = d2 + (i - n0 - n1); }
    else return;
    float4 v = *s;
    __half2 a = __halves2half2(__float2half_rn(v.x), __float2half_rn(v.y));
    __half2 b = __halves2half2(__float2half_rn(v.z), __float2half_rn(v.w));
    uint2 o;
    o.x = *(const uint32_t*)&a; o.y = *(const uint32_t*)&b;
    *d = o;
}

// ---------------- stage loader -----------------------------------------------
__device__ __forceinline__ void load_tile(
    const __half* __restrict__ A, const __half* __restrict__ Bm,
    int bm, int bn, int Nb, int K, int kt, int s, uint32_t sbase, int tid)
{
    uint32_t stg = sbase + (uint32_t)s * 2 * TILE_B;
    const uint32_t aT = stg;
    const uint32_t bT = stg + TILE_B;

    const size_t aoff = (size_t)bm * K + (size_t)kt * BK;
#pragma unroll
    for (int i = 0; i < 4; i++) {
        int c = tid + i * 256;
        int r = c >> 3, ch = c & 7;
        cpa16(aT + (uint32_t)(r * LDT + ch * 8) * 2,
              A + aoff + (size_t)r * K + ch * 8, 16);
    }
    const size_t boff = (size_t)kt * BK;
#pragma unroll
    for (int i = 0; i < 4; i++) {
        int c = tid + i * 256;
        int r = c >> 3, ch = c & 7;
        int grow = bn + r;
        int ok = (grow < Nb) ? 16 : 0;
        if (grow >= Nb) grow = Nb - 1;
        cpa16(bT + (uint32_t)(r * LDT + ch * 8) * 2,
              Bm + boff + (size_t)grow * K + ch * 8, ok);
    }
}

// ---------------- fp16 mma.sync GEMM: C = A @ B^T + epilogue -----------------
// EPI 0: logits -> float C;  EPI 1: relu+bias -> fp16 C;  EPI 2: bias -> float C
template<int EPI>
__global__ __launch_bounds__(256)
void tc_gemm(const __half* __restrict__ A, const __half* __restrict__ Bm,
             void* __restrict__ Cv, int Nb, int K,
             const float* __restrict__ aux0, const float* __restrict__ aux1)
{
    extern __shared__ char dsm[];
    const int tid  = threadIdx.x;
    const int wid  = tid >> 5;
    const int lane = tid & 31;
    const int wm   = wid & 3;
    const int wn   = wid >> 2;
    const int bm   = blockIdx.x * BM;
    const int bn   = blockIdx.y * BN;
    const uint32_t sbase = smem_u32(dsm);

    float acc[2][8][4];
#pragma unroll
    for (int mt = 0; mt < 2; mt++)
#pragma unroll
        for (int nt = 0; nt < 8; nt++)
#pragma unroll
            for (int i = 0; i < 4; i++) acc[mt][nt][i] = 0.f;

    const int T = K / BK;
    const int lrow = lane & 15;
    const int lcol = (lane >> 4) * 8;

    // stage-invariant byte offsets (hoisted out of the mainloop)
    uint32_t aro[2], bro[4];
#pragma unroll
    for (int mt = 0; mt < 2; mt++)
        aro[mt] = (uint32_t)((wm * 32 + mt * 16 + lrow) * LDT) * 2;
#pragma unroll
    for (int np = 0; np < 4; np++)
        bro[np] = (uint32_t)((wn * 64 + np * 16 + lrow) * LDT) * 2 + TILE_B;

#pragma unroll
    for (int p = 0; p < STG - 1; p++) {
        load_tile(A, Bm, bm, bn, Nb, K, p, p, sbase, tid);
        cpa_commit();
    }

    uint32_t ah[2][2][4];
    uint32_t bh[2][8][2];

    for (int t = 0; t < T; t++) {
        asm volatile("cp.async.wait_group %0;" :: "n"(STG - 2) : "memory");
        __syncthreads();

        int tn = t + STG - 1;
        if (tn < T)
            load_tile(A, Bm, bm, bn, Nb, K, tn, tn % STG, sbase, tid);
        cpa_commit();

        const uint32_t stg = sbase + (uint32_t)(t % STG) * 2 * TILE_B;

        auto ldfr = [&](int bu, int ks) {
            uint32_t fo = stg + (uint32_t)(ks * 16 + lcol) * 2;
#pragma unroll
            for (int mt = 0; mt < 2; mt++)
                ldm_x4(ah[bu][mt][0], ah[bu][mt][1], ah[bu][mt][2], ah[bu][mt][3],
                       fo + aro[mt]);
#pragma unroll
            for (int np = 0; np < 4; np++) {
                uint32_t r0, r1, r2, r3;
                ldm_x4(r0, r1, r2, r3, fo + bro[np]);
                bh[bu][2*np][0] = r0; bh[bu][2*np+1][0] = r1;
                bh[bu][2*np][1] = r2; bh[bu][2*np+1][1] = r3;
            }
        };

        ldfr(0, 0);
#pragma unroll
        for (int ks = 0; ks < BK / 16; ks++) {
            int cur = ks & 1;
            if (ks + 1 < BK / 16) ldfr(cur ^ 1, ks + 1);
#pragma unroll
            for (int mt = 0; mt < 2; mt++)
#pragma unroll
                for (int nt = 0; nt < 8; nt++)
                    mma16816(acc[mt][nt], ah[cur][mt], bh[cur][nt]);
        }
    }

    // ---- epilogue ----
    const int r0 = lane >> 2;
    const int c0 = (lane & 3) * 2;
#pragma unroll
    for (int mt = 0; mt < 2; mt++) {
#pragma unroll
        for (int nt = 0; nt < 8; nt++) {
#pragma unroll
            for (int half = 0; half < 2; half++) {
                int m = bm + wm * 32 + mt * 16 + r0 + half * 8;
#pragma unroll
                for (int e = 0; e < 2; e++) {
                    int n = bn + wn * 64 + nt * 8 + c0 + e;
                    if (n >= Nb) continue;
                    float v = acc[mt][nt][half * 2 + e];
                    if (EPI == 0) {
                        float d2 = aux0[m] + aux1[n] - 2.f * (v * INV_SCALE);
                        ((float*)Cv)[(size_t)m * Nb + n] =
                            -TEMP_INV * sqrtf(fmaxf(d2, 1e-12f));
                    } else if (EPI == 1) {
                        ((__half*)Cv)[(size_t)m * Nb + n] =
                            __float2half_rn(fmaxf(v + aux0[n], 0.f));
                    } else {
                        ((float*)Cv)[(size_t)m * Nb + n] = v + aux0[n];
                    }
                }
            }
        }
    }
}

// ---------------- softmax (fp16 out) + candidate emission --------------------
__global__ __launch_bounds__(256)
void softmax_kernel(const float* __restrict__ S, __half* __restrict__ Sb,
                    int* __restrict__ candbuf, int* __restrict__ ncand)
{
    const int row = blockIdx.x;
    const int tid = threadIdx.x;
    const float4* p4 = (const float4*)(S + (size_t)row * HDIM);

    __shared__ float sv[256];
    __shared__ int snc;

    float4 v4[4];
    float best = -1e30f;
#pragma unroll
    for (int t = 0; t < 4; t++) {
        v4[t] = p4[tid + t * 256];
        best = fmaxf(best, fmaxf(fmaxf(v4[t].x, v4[t].y), fmaxf(v4[t].z, v4[t].w)));
    }
    sv[tid] = best;
    if (tid == 0) snc = 0;
    __syncthreads();
    for (int st = 128; st > 0; st >>= 1) {
        if (tid < st) sv[tid] = fmaxf(sv[tid], sv[tid + st]);
        __syncthreads();
    }
    const float mx = sv[0];
    __syncthreads();

    const float thr = mx - MARGIN;
#pragma unroll
    for (int t = 0; t < 4; t++) {
        int base = (tid + t * 256) * 4;
        float vv[4] = {v4[t].x, v4[t].y, v4[t].z, v4[t].w};
#pragma unroll
        for (int j = 0; j < 4; j++)
            if (vv[j] >= thr) {
                int slot = atomicAdd(&snc, 1);
                if (slot < MAXC) candbuf[(size_t)row * MAXC + slot] = base + j;
            }
    }

    float s = 0.f;
#pragma unroll
    for (int t = 0; t < 4; t++) {
        v4[t].x = __expf(v4[t].x - mx);
        v4[t].y = __expf(v4[t].y - mx);
        v4[t].z = __expf(v4[t].z - mx);
        v4[t].w = __expf(v4[t].w - mx);
        s += (v4[t].x + v4[t].y) + (v4[t].z + v4[t].w);
    }
    sv[tid] = s;
    __syncthreads();
    for (int st = 128; st > 0; st >>= 1) {
        if (tid < st) sv[tid] += sv[tid + st];
        __syncthreads();
    }
    const float inv = 1.f / sv[0];
    if (tid == 0) ncand[row] = snc < MAXC ? snc : MAXC;

    uint2* ob = (uint2*)(Sb + (size_t)row * HDIM);
#pragma unroll
    for (int t = 0; t < 4; t++) {
        __half2 a = __halves2half2(__float2half_rn(v4[t].x * inv), __float2half_rn(v4[t].y * inv));
        __half2 b = __halves2half2(__float2half_rn(v4[t].z * inv), __float2half_rn(v4[t].w * inv));
        uint2 u;
        u.x = *(const uint32_t*)&a; u.y = *(const uint32_t*)&b;
        ob[tid + t * 256] = u;
    }
}

// ---------------- winner recheck (1 warp per row; runs overlapped) -----------
__global__ __launch_bounds__(256)
void recheck_kernel(const int* __restrict__ candbuf, const int* __restrict__ ncand,
                    float* __restrict__ winners,
                    const float* __restrict__ x, const float* __restrict__ W,
                    const float* __restrict__ x2v, const float* __restrict__ w2v)
{
    const int wid = threadIdx.x >> 5;
    const int lane = threadIdx.x & 31;
    const int row = blockIdx.x * 8 + wid;
    if (row >= BROWS) return;

    const float* xr = x + (size_t)row * DIN;
    const int nc = ncand[row];
    float bd = 3.4e38f;
    int bidx = 0x7fffffff;
    for (int c = 0; c < nc; c++) {
        int idx = candbuf[(size_t)row * MAXC + c];
        const float* wr = W + (size_t)idx * DIN;
        float s2 = 0.f;
        for (int k = lane; k < DIN; k += 32) s2 = fmaf(xr[k], wr[k], s2);
#pragma unroll
        for (int off = 16; off > 0; off >>= 1)
            s2 += __shfl_xor_sync(0xffffffff, s2, off);
        float d2 = x2v[row] + w2v[idx] - 2.f * s2;
        float d = sqrtf(fmaxf(d2, 1e-12f));
        if (d < bd || (d == bd && idx < bidx)) { bd = d; bidx = idx; }
    }
    if (lane == 0) winners[row] = (float)bidx;
}

// ---------------- launcher --------------------------------------------------
extern "C" void kernel_launch(void* const* d_in, const int* in_sizes, int n_in,
                              void* d_out, int out_size)
{
    const float* x  = (const float*)d_in[0];
    const float* W  = (const float*)d_in[1];
    const float* w1 = (const float*)d_in[2];
    const float* b1 = (const float*)d_in[3];
    const float* w2 = (const float*)d_in[4];
    const float* b2 = (const float*)d_in[5];
    const float* w3 = (const float*)d_in[6];
    const float* b3 = (const float*)d_in[7];
    float* out = (float*)d_out;

    float *S, *x2, *wsq;
    __half *Sb, *h1, *h2, *xh, *Wh, *w1h, *w2h, *w3h;
    int *cand, *ncv;
    cudaGetSymbolAddress((void**)&S,   g_S);
    cudaGetSymbolAddress((void**)&Sb,  g_Sb);
    cudaGetSymbolAddress((void**)&h1,  g_h1);
    cudaGetSymbolAddress((void**)&h2,  g_h2);
    cudaGetSymbolAddress((void**)&xh,  g_xh);
    cudaGetSymbolAddress((void**)&Wh,  g_Wh);
    cudaGetSymbolAddress((void**)&w1h, g_w1h);
    cudaGetSymbolAddress((void**)&w2h, g_w2h);
    cudaGetSymbolAddress((void**)&w3h, g_w3h);
    cudaGetSymbolAddress((void**)&x2,  g_x2);
    cudaGetSymbolAddress((void**)&wsq, g_w2s);
    cudaGetSymbolAddress((void**)&cand, g_cand);
    cudaGetSymbolAddress((void**)&ncv,  g_nc);

    cudaFuncSetAttribute(tc_gemm<0>, cudaFuncAttributeMaxDynamicSharedMemorySize, SMEM_STD);
    cudaFuncSetAttribute(tc_gemm<1>, cudaFuncAttributeMaxDynamicSharedMemorySize, SMEM_STD);
    cudaFuncSetAttribute(tc_gemm<2>, cudaFuncAttributeMaxDynamicSharedMemorySize, SMEM_STD);

    float* winners = out + (size_t)out_size - BROWS;

    // side stream + events (created once, on the first/non-capture call)
    static cudaStream_t s2 = nullptr;
    static cudaEvent_t evA = nullptr, evB = nullptr, evC = nullptr, evD = nullptr;
    if (!s2) {
        cudaStreamCreateWithFlags(&s2, cudaStreamNonBlocking);
        cudaEventCreateWithFlags(&evA, cudaEventDisableTiming);
        cudaEventCreateWithFlags(&evB, cudaEventDisableTiming);
        cudaEventCreateWithFlags(&evC, cudaEventDisableTiming);
        cudaEventCreateWithFlags(&evD, cudaEventDisableTiming);
    }

    // Fork the side stream FROM the capture stream at the very top (legal
    // capture edge), so f2h3 overlaps convsq + gemm0.
    cudaEventRecord(evA, 0);
    cudaStreamWaitEvent(s2, evA, 0);
    {
        int n0 = H1DIM * HDIM / 4, n1 = H2DIM * H1DIM / 4, n2 = OUTD * H2DIM / 4;
        f2h3_kernel<<<(n0 + n1 + n2 + 255) / 256, 256, 0, s2>>>(
            (const float4*)w1, (uint2*)w1h, n0,
            (const float4*)w2, (uint2*)w2h, n1,
            (const float4*)w3, (uint2*)w3h, n2);
    }
    cudaEventRecord(evB, s2);

    // main: convsq -> gemm0 -> softmax -> [wait w1h] gemm1 -> gemm2 -> gemm3
    convsq_kernel<<<BROWS + HDIM, 256>>>(x, W, xh, Wh, x2, wsq);
    tc_gemm<0><<<dim3(BROWS / BM, HDIM / BN), 256, SMEM_STD>>>(
        xh, Wh, S, HDIM, DIN, x2, wsq);
    softmax_kernel<<<BROWS, 256>>>(S, Sb, cand, ncv);

    cudaEventRecord(evC, 0);
    cudaStreamWaitEvent(s2, evC, 0);
    recheck_kernel<<<BROWS / 8, 256, 0, s2>>>(cand, ncv, winners, x, W, x2, wsq);
    cudaEventRecord(evD, s2);

    cudaStreamWaitEvent(0, evB, 0);   // gemm1 needs w1h/w2h/w3h
    tc_gemm<1><<<dim3(BROWS / BM, H1DIM / BN), 256, SMEM_STD>>>(
        Sb, w1h, h1, H1DIM, HDIM, b1, nullptr);
    tc_gemm<1><<<dim3(BROWS / BM, H2DIM / BN), 256, SMEM_STD>>>(
        h1, w2h, h2, H2DIM, H1DIM, b2, nullptr);
    tc_gemm<2><<<dim3(BROWS / BM, (OUTD + BN - 1) / BN), 256, SMEM_STD>>>(
        h2, w3h, out, OUTD, H2DIM, b3, nullptr);
    cudaStreamWaitEvent(0, evD, 0);   // join: winners complete before graph end
}

// round 17
// speedup vs baseline: 5.7448x; 1.0058x over previous
#include <cuda_runtime.h>
#include <cuda_fp16.h>
#include <math.h>
#include <stdint.h>

// Problem dims (fixed by dataset)
#define BROWS 4096
#define HDIM  4096
#define DIN   2048
#define H1DIM 2048
#define H2DIM 1024
#define OUTD  1000
#define TEMP_INV 2.0f       // 1/TEMPERATURE
#define XSCALE 32.0f
#define WSCALE 64.0f
#define INV_SCALE (1.0f / 2048.0f)   // 1/(XSCALE*WSCALE), exact power of 2
#define MARGIN 0.005f       // logit margin for winner recheck (~140 sigma of fp16 noise)
#define MAXC 16             // candidate cap per row

// GEMM tiling (fp16 mma.sync m16n8k16)
#define BM 128
#define BN 128
#define BK 64
#define PAD 8
#define LDT (BK + PAD)                       // 72 halves per smem row (144 B)
#define TILE_B (128 * LDT * 2)               // one 128-row tile: 18432 B
#define STG 3
#define SMEM_STD (STG * 2 * TILE_B)          // 110592 B -> 2 CTAs/SM

// ---------------- scratch (static device globals; no allocs allowed) --------
__device__ float  g_S  [(size_t)BROWS * HDIM];   // fp32 logits
__device__ __half g_Sb [(size_t)BROWS * HDIM];   // fp16 softmax
__device__ __half g_h1 [(size_t)BROWS * H1DIM];
__device__ __half g_h2 [(size_t)BROWS * H2DIM];
__device__ __half g_xh [(size_t)BROWS * DIN];
__device__ __half g_Wh [(size_t)HDIM * DIN];
__device__ __half g_w1h[(size_t)H1DIM * HDIM];
__device__ __half g_w2h[(size_t)H2DIM * H1DIM];
__device__ __half g_w3h[(size_t)OUTD * H2DIM];
__device__ float  g_x2[BROWS];
__device__ float  g_w2s[HDIM];
__device__ int    g_cand[(size_t)BROWS * MAXC];
__device__ int    g_nc[BROWS];

// ---------------- PTX helpers ------------------------------------------------
__device__ __forceinline__ uint32_t smem_u32(const void* p) {
    uint32_t a;
    asm("{ .reg .u64 t; cvta.to.shared.u64 t, %1; cvt.u32.u64 %0, t; }"
        : "=r"(a) : "l"(p));
    return a;
}
__device__ __forceinline__ void cpa16(uint32_t s, const void* g, int sz) {
    asm volatile("cp.async.cg.shared.global [%0], [%1], 16, %2;"
                 :: "r"(s), "l"(g), "r"(sz));
}
__device__ __forceinline__ void cpa16f(uint32_t s, const void* g) {   // full 16B, no predicate
    asm volatile("cp.async.cg.shared.global [%0], [%1], 16;"
                 :: "r"(s), "l"(g));
}
__device__ __forceinline__ void cpa_commit() {
    asm volatile("cp.async.commit_group;" ::: "memory");
}
__device__ __forceinline__ void ldm_x4(uint32_t& r0, uint32_t& r1,
                                       uint32_t& r2, uint32_t& r3, uint32_t addr) {
    asm volatile("ldmatrix.sync.aligned.m8n8.x4.shared.b16 {%0,%1,%2,%3}, [%4];"
                 : "=r"(r0), "=r"(r1), "=r"(r2), "=r"(r3) : "r"(addr));
}
__device__ __forceinline__ void mma16816(float* c, const uint32_t* a, const uint32_t* b) {
    asm volatile(
        "mma.sync.aligned.m16n8k16.row.col.f32.f16.f16.f32 "
        "{%0,%1,%2,%3}, {%4,%5,%6,%7}, {%8,%9}, {%0,%1,%2,%3};"
        : "+f"(c[0]), "+f"(c[1]), "+f"(c[2]), "+f"(c[3])
        : "r"(a[0]), "r"(a[1]), "r"(a[2]), "r"(a[3]), "r"(b[0]), "r"(b[1]));
}

// ---------------- fused convert(+scale) + row sum-of-squares -----------------
__global__ void convsq_kernel(const float* __restrict__ X, const float* __restrict__ W,
                              __half* __restrict__ xh, __half* __restrict__ Wh,
                              float* __restrict__ ox, float* __restrict__ ow)
{
    int row = blockIdx.x;
    const float* p;
    __half* d;
    float scale;
    float* o;
    if (row < BROWS) { p = X + (size_t)row * DIN; d = xh + (size_t)row * DIN; scale = XSCALE; o = ox + row; }
    else { int r = row - BROWS; p = W + (size_t)r * DIN; d = Wh + (size_t)r * DIN; scale = WSCALE; o = ow + r; }

    for (int i = threadIdx.x; i < DIN / 4; i += 256) {
        float4 v = ((const float4*)p)[i];
        __half2 a = __halves2half2(__float2half_rn(v.x * scale), __float2half_rn(v.y * scale));
        __half2 b = __halves2half2(__float2half_rn(v.z * scale), __float2half_rn(v.w * scale));
        uint2 u;
        u.x = *(const uint32_t*)&a; u.y = *(const uint32_t*)&b;
        ((uint2*)d)[i] = u;
    }
    float s = 0.f;
    for (int i = threadIdx.x; i < DIN; i += 256) {
        float v = p[i];
        s = fmaf(v, v, s);
    }
    __shared__ float red[256];
    red[threadIdx.x] = s;
    __syncthreads();
    for (int st = 128; st > 0; st >>= 1) {
        if (threadIdx.x < st) red[threadIdx.x] += red[threadIdx.x + st];
        __syncthreads();
    }
    if (threadIdx.x == 0) *o = red[0];
}

// convert three weight arrays in one launch
__global__ void f2h3_kernel(const float4* __restrict__ s0, uint2* __restrict__ d0, int n0,
                            const float4* __restrict__ s1, uint2* __restrict__ d1, int n1,
                            const float4* __restrict__ s2, uint2* __restrict__ d2, int n2)
{
    int i = blockIdx.x * 256 + threadIdx.x;
    const float4* s; uint2* d;
    if (i < n0) { s = s0 + i; d = d0 + i; }
    else if (i < n0 + n1) { s = s1 + (i - n0); d = d1 + (i - n0); }
    else if (i < n0 + n1 + n2) { s = s2 + (i - n0 - n1); d = d2 + (i - n0 - n1); }
    else return;
    float4 v = *s;
    __half2 a = __halves2half2(__float2half_rn(v.x), __float2half_rn(v.y));
    __half2 b = __halves2half2(__float2half_rn(v.z), __float2half_rn(v.w));
    uint2 o;
    o.x = *(const uint32_t*)&a; o.y = *(const uint32_t*)&b;
    *d = o;
}

// ---------------- stage loader -----------------------------------------------
// BOUND=false: Nb is a multiple of 128 -> no clamping/predication (gemm0/1/2).
template<bool BOUND>
__device__ __forceinline__ void load_tile(
    const __half* __restrict__ A, const __half* __restrict__ Bm,
    int bm, int bn, int Nb, int K, int kt, int s, uint32_t sbase, int tid)
{
    uint32_t stg = sbase + (uint32_t)s * 2 * TILE_B;
    const uint32_t aT = stg;
    const uint32_t bT = stg + TILE_B;

    const size_t aoff = (size_t)bm * K + (size_t)kt * BK;
#pragma unroll
    for (int i = 0; i < 4; i++) {
        int c = tid + i * 256;
        int r = c >> 3, ch = c & 7;
        cpa16f(aT + (uint32_t)(r * LDT + ch * 8) * 2,
               A + aoff + (size_t)r * K + ch * 8);
    }
    const size_t boff = (size_t)kt * BK;
#pragma unroll
    for (int i = 0; i < 4; i++) {
        int c = tid + i * 256;
        int r = c >> 3, ch = c & 7;
        int grow = bn + r;
        if (BOUND) {
            int ok = (grow < Nb) ? 16 : 0;
            if (grow >= Nb) grow = Nb - 1;
            cpa16(bT + (uint32_t)(r * LDT + ch * 8) * 2,
                  Bm + boff + (size_t)grow * K + ch * 8, ok);
        } else {
            cpa16f(bT + (uint32_t)(r * LDT + ch * 8) * 2,
                   Bm + boff + (size_t)grow * K + ch * 8);
        }
    }
}

// ---------------- fp16 mma.sync GEMM: C = A @ B^T + epilogue -----------------
// EPI 0: logits -> float C;  EPI 1: relu+bias -> fp16 C;  EPI 2: bias -> float C
template<int EPI, bool BOUND>
__global__ __launch_bounds__(256)
void tc_gemm(const __half* __restrict__ A, const __half* __restrict__ Bm,
             void* __restrict__ Cv, int Nb, int K,
             const float* __restrict__ aux0, const float* __restrict__ aux1)
{
    extern __shared__ char dsm[];
    const int tid  = threadIdx.x;
    const int wid  = tid >> 5;
    const int lane = tid & 31;
    const int wm   = wid & 3;
    const int wn   = wid >> 2;
    const int bm   = blockIdx.x * BM;
    const int bn   = blockIdx.y * BN;
    const uint32_t sbase = smem_u32(dsm);

    float acc[2][8][4];
#pragma unroll
    for (int mt = 0; mt < 2; mt++)
#pragma unroll
        for (int nt = 0; nt < 8; nt++)
#pragma unroll
            for (int i = 0; i < 4; i++) acc[mt][nt][i] = 0.f;

    const int T = K / BK;
    const int lrow = lane & 15;
    const int lcol = (lane >> 4) * 8;

    // stage-invariant byte offsets (hoisted out of the mainloop)
    uint32_t aro[2], bro[4];
#pragma unroll
    for (int mt = 0; mt < 2; mt++)
        aro[mt] = (uint32_t)((wm * 32 + mt * 16 + lrow) * LDT) * 2;
#pragma unroll
    for (int np = 0; np < 4; np++)
        bro[np] = (uint32_t)((wn * 64 + np * 16 + lrow) * LDT) * 2 + TILE_B;

#pragma unroll
    for (int p = 0; p < STG - 1; p++) {
        load_tile<BOUND>(A, Bm, bm, bn, Nb, K, p, p, sbase, tid);
        cpa_commit();
    }

    uint32_t ah[2][2][4];
    uint32_t bh[2][8][2];

    for (int t = 0; t < T; t++) {
        asm volatile("cp.async.wait_group %0;" :: "n"(STG - 2) : "memory");
        __syncthreads();

        int tn = t + STG - 1;
        if (tn < T)
            load_tile<BOUND>(A, Bm, bm, bn, Nb, K, tn, tn % STG, sbase, tid);
        cpa_commit();

        const uint32_t stg = sbase + (uint32_t)(t % STG) * 2 * TILE_B;

        auto ldfr = [&](int bu, int ks) {
            uint32_t fo = stg + (uint32_t)(ks * 16 + lcol) * 2;
#pragma unroll
            for (int mt = 0; mt < 2; mt++)
                ldm_x4(ah[bu][mt][0], ah[bu][mt][1], ah[bu][mt][2], ah[bu][mt][3],
                       fo + aro[mt]);
#pragma unroll
            for (int np = 0; np < 4; np++) {
                uint32_t r0, r1, r2, r3;
                ldm_x4(r0, r1, r2, r3, fo + bro[np]);
                bh[bu][2*np][0] = r0; bh[bu][2*np+1][0] = r1;
                bh[bu][2*np][1] = r2; bh[bu][2*np+1][1] = r3;
            }
        };

        ldfr(0, 0);
#pragma unroll
        for (int ks = 0; ks < BK / 16; ks++) {
            int cur = ks & 1;
            if (ks + 1 < BK / 16) ldfr(cur ^ 1, ks + 1);
#pragma unroll
            for (int mt = 0; mt < 2; mt++)
#pragma unroll
                for (int nt = 0; nt < 8; nt++)
                    mma16816(acc[mt][nt], ah[cur][mt], bh[cur][nt]);
        }
    }

    // ---- epilogue ----
    const int r0 = lane >> 2;
    const int c0 = (lane & 3) * 2;
#pragma unroll
    for (int mt = 0; mt < 2; mt++) {
#pragma unroll
        for (int nt = 0; nt < 8; nt++) {
#pragma unroll
            for (int half = 0; half < 2; half++) {
                int m = bm + wm * 32 + mt * 16 + r0 + half * 8;
#pragma unroll
                for (int e = 0; e < 2; e++) {
                    int n = bn + wn * 64 + nt * 8 + c0 + e;
                    if (BOUND && n >= Nb) continue;
                    float v = acc[mt][nt][half * 2 + e];
                    if (EPI == 0) {
                        float d2 = aux0[m] + aux1[n] - 2.f * (v * INV_SCALE);
                        ((float*)Cv)[(size_t)m * Nb + n] =
                            -TEMP_INV * sqrtf(fmaxf(d2, 1e-12f));
                    } else if (EPI == 1) {
                        ((__half*)Cv)[(size_t)m * Nb + n] =
                            __float2half_rn(fmaxf(v + aux0[n], 0.f));
                    } else {
                        ((float*)Cv)[(size_t)m * Nb + n] = v + aux0[n];
                    }
                }
            }
        }
    }
}

// ---------------- softmax (fp16 out) + candidate emission --------------------
__global__ __launch_bounds__(256)
void softmax_kernel(const float* __restrict__ S, __half* __restrict__ Sb,
                    int* __restrict__ candbuf, int* __restrict__ ncand)
{
    const int row = blockIdx.x;
    const int tid = threadIdx.x;
    const float4* p4 = (const float4*)(S + (size_t)row * HDIM);

    __shared__ float sv[256];
    __shared__ int snc;

    float4 v4[4];
    float best = -1e30f;
#pragma unroll
    for (int t = 0; t < 4; t++) {
        v4[t] = p4[tid + t * 256];
        best = fmaxf(best, fmaxf(fmaxf(v4[t].x, v4[t].y), fmaxf(v4[t].z, v4[t].w)));
    }
    sv[tid] = best;
    if (tid == 0) snc = 0;
    __syncthreads();
    for (int st = 128; st > 0; st >>= 1) {
        if (tid < st) sv[tid] = fmaxf(sv[tid], sv[tid + st]);
        __syncthreads();
    }
    const float mx = sv[0];
    __syncthreads();

    const float thr = mx - MARGIN;
#pragma unroll
    for (int t = 0; t < 4; t++) {
        int base = (tid + t * 256) * 4;
        float vv[4] = {v4[t].x, v4[t].y, v4[t].z, v4[t].w};
#pragma unroll
        for (int j = 0; j < 4; j++)
            if (vv[j] >= thr) {
                int slot = atomicAdd(&snc, 1);
                if (slot < MAXC) candbuf[(size_t)row * MAXC + slot] = base + j;
            }
    }

    float s = 0.f;
#pragma unroll
    for (int t = 0; t < 4; t++) {
        v4[t].x = __expf(v4[t].x - mx);
        v4[t].y = __expf(v4[t].y - mx);
        v4[t].z = __expf(v4[t].z - mx);
        v4[t].w = __expf(v4[t].w - mx);
        s += (v4[t].x + v4[t].y) + (v4[t].z + v4[t].w);
    }
    sv[tid] = s;
    __syncthreads();
    for (int st = 128; st > 0; st >>= 1) {
        if (tid < st) sv[tid] += sv[tid + st];
        __syncthreads();
    }
    const float inv = 1.f / sv[0];
    if (tid == 0) ncand[row] = snc < MAXC ? snc : MAXC;

    uint2* ob = (uint2*)(Sb + (size_t)row * HDIM);
#pragma unroll
    for (int t = 0; t < 4; t++) {
        __half2 a = __halves2half2(__float2half_rn(v4[t].x * inv), __float2half_rn(v4[t].y * inv));
        __half2 b = __halves2half2(__float2half_rn(v4[t].z * inv), __float2half_rn(v4[t].w * inv));
        uint2 u;
        u.x = *(const uint32_t*)&a; u.y = *(const uint32_t*)&b;
        ob[tid + t * 256] = u;
    }
}

// ---------------- winner recheck (1 warp per row; runs overlapped) -----------
__global__ __launch_bounds__(256)
void recheck_kernel(const int* __restrict__ candbuf, const int* __restrict__ ncand,
                    float* __restrict__ winners,
                    const float* __restrict__ x, const float* __restrict__ W,
                    const float* __restrict__ x2v, const float* __restrict__ w2v)
{
    const int wid = threadIdx.x >> 5;
    const int lane = threadIdx.x & 31;
    const int row = blockIdx.x * 8 + wid;
    if (row >= BROWS) return;

    const float4* xr = (const float4*)(x + (size_t)row * DIN);
    const int nc = ncand[row];
    float bd = 3.4e38f;
    int bidx = 0x7fffffff;
    for (int c = 0; c < nc; c++) {
        int idx = candbuf[(size_t)row * MAXC + c];
        const float4* wr = (const float4*)(W + (size_t)idx * DIN);
        float s2 = 0.f;
        for (int k = lane; k < DIN / 4; k += 32) {
            float4 a = xr[k], b = wr[k];
            s2 = fmaf(a.x, b.x, s2);
            s2 = fmaf(a.y, b.y, s2);
            s2 = fmaf(a.z, b.z, s2);
            s2 = fmaf(a.w, b.w, s2);
        }
#pragma unroll
        for (int off = 16; off > 0; off >>= 1)
            s2 += __shfl_xor_sync(0xffffffff, s2, off);
        float d2 = x2v[row] + w2v[idx] - 2.f * s2;
        float d = sqrtf(fmaxf(d2, 1e-12f));
        if (d < bd || (d == bd && idx < bidx)) { bd = d; bidx = idx; }
    }
    if (lane == 0) winners[row] = (float)bidx;
}

// ---------------- launcher --------------------------------------------------
extern "C" void kernel_launch(void* const* d_in, const int* in_sizes, int n_in,
                              void* d_out, int out_size)
{
    const float* x  = (const float*)d_in[0];
    const float* W  = (const float*)d_in[1];
    const float* w1 = (const float*)d_in[2];
    const float* b1 = (const float*)d_in[3];
    const float* w2 = (const float*)d_in[4];
    const float* b2 = (const float*)d_in[5];
    const float* w3 = (const float*)d_in[6];
    const float* b3 = (const float*)d_in[7];
    float* out = (float*)d_out;

    float *S, *x2, *wsq;
    __half *Sb, *h1, *h2, *xh, *Wh, *w1h, *w2h, *w3h;
    int *cand, *ncv;
    cudaGetSymbolAddress((void**)&S,   g_S);
    cudaGetSymbolAddress((void**)&Sb,  g_Sb);
    cudaGetSymbolAddress((void**)&h1,  g_h1);
    cudaGetSymbolAddress((void**)&h2,  g_h2);
    cudaGetSymbolAddress((void**)&xh,  g_xh);
    cudaGetSymbolAddress((void**)&Wh,  g_Wh);
    cudaGetSymbolAddress((void**)&w1h, g_w1h);
    cudaGetSymbolAddress((void**)&w2h, g_w2h);
    cudaGetSymbolAddress((void**)&w3h, g_w3h);
    cudaGetSymbolAddress((void**)&x2,  g_x2);
    cudaGetSymbolAddress((void**)&wsq, g_w2s);
    cudaGetSymbolAddress((void**)&cand, g_cand);
    cudaGetSymbolAddress((void**)&ncv,  g_nc);

    cudaFuncSetAttribute(tc_gemm<0,false>, cudaFuncAttributeMaxDynamicSharedMemorySize, SMEM_STD);
    cudaFuncSetAttribute(tc_gemm<1,false>, cudaFuncAttributeMaxDynamicSharedMemorySize, SMEM_STD);
    cudaFuncSetAttribute(tc_gemm<2,true>,  cudaFuncAttributeMaxDynamicSharedMemorySize, SMEM_STD);

    float* winners = out + (size_t)out_size - BROWS;

    // side stream + events (created once, on the first/non-capture call)
    static cudaStream_t s2 = nullptr;
    static cudaEvent_t evA = nullptr, evB = nullptr, evC = nullptr, evD = nullptr;
    if (!s2) {
        cudaStreamCreateWithFlags(&s2, cudaStreamNonBlocking);
        cudaEventCreateWithFlags(&evA, cudaEventDisableTiming);
        cudaEventCreateWithFlags(&evB, cudaEventDisableTiming);
        cudaEventCreateWithFlags(&evC, cudaEventDisableTiming);
        cudaEventCreateWithFlags(&evD, cudaEventDisableTiming);
    }

    // Fork the side stream FROM the capture stream at the very top (legal
    // capture edge), so f2h3 overlaps convsq + gemm0.
    cudaEventRecord(evA, 0);
    cudaStreamWaitEvent(s2, evA, 0);
    {
        int n0 = H1DIM * HDIM / 4, n1 = H2DIM * H1DIM / 4, n2 = OUTD * H2DIM / 4;
        f2h3_kernel<<<(n0 + n1 + n2 + 255) / 256, 256, 0, s2>>>(
            (const float4*)w1, (uint2*)w1h, n0,
            (const float4*)w2, (uint2*)w2h, n1,
            (const float4*)w3, (uint2*)w3h, n2);
    }
    cudaEventRecord(evB, s2);

    // main: convsq -> gemm0 -> softmax -> [wait w1h] gemm1 -> gemm2 -> gemm3
    convsq_kernel<<<BROWS + HDIM, 256>>>(x, W, xh, Wh, x2, wsq);
    tc_gemm<0,false><<<dim3(BROWS / BM, HDIM / BN), 256, SMEM_STD>>>(
        xh, Wh, S, HDIM, DIN, x2, wsq);
    softmax_kernel<<<BROWS, 256>>>(S, Sb, cand, ncv);

    cudaEventRecord(evC, 0);
    cudaStreamWaitEvent(s2, evC, 0);
    recheck_kernel<<<BROWS / 8, 256, 0, s2>>>(cand, ncv, winners, x, W, x2, wsq);
    cudaEventRecord(evD, s2);

    cudaStreamWaitEvent(0, evB, 0);   // gemm1 needs w1h/w2h/w3h
    tc_gemm<1,false><<<dim3(BROWS / BM, H1DIM / BN), 256, SMEM_STD>>>(
        Sb, w1h, h1, H1DIM, HDIM, b1, nullptr);
    tc_gemm<1,false><<<dim3(BROWS / BM, H2DIM / BN), 256, SMEM_STD>>>(
        h1, w2h, h2, H2DIM, H1DIM, b2, nullptr);
    tc_gemm<2,true><<<dim3(BROWS / BM, (OUTD + BN - 1) / BN), 256, SMEM_STD>>>(
        h2, w3h, out, OUTD, H2DIM, b3, nullptr);
    cudaStreamWaitEvent(0, evD, 0);   // join: winners complete before graph end
}